// round 2
// baseline (speedup 1.0000x reference)
#include <cuda_runtime.h>
#include <cuda_bf16.h>
#include <math.h>

// Problem constants
#define BB 2
#define TT 2048
#define DM 1024
#define HH 16
#define DD 64
#define NQKV 5120     // H * 5 * D
#define BT  4096      // B * T

// ---------------- scratch (no cudaMalloc allowed) ----------------
__device__ __align__(16) float g_qkv[(size_t)BT * NQKV];   // 83.9 MB
__device__ __align__(16) float g_attn[(size_t)BT * DM];    // 16.8 MB

// ---------------- classic fp32 SGEMM: 128x128x8, 8x8 microtile ----------------
__global__ void __launch_bounds__(256) sgemm128(const float* __restrict__ A,
                                                const float* __restrict__ B,
                                                float* __restrict__ C,
                                                int M, int N, int K) {
    __shared__ float As[8][128];
    __shared__ float Bs[8][128];

    const int tid  = threadIdx.x;
    const int brow = blockIdx.y;
    const int bcol = blockIdx.x;

    const float* Ab = A + (size_t)brow * 128 * K;
    const float* Bb = B + (size_t)bcol * 128;

    const int aRow = tid >> 1;           // 0..127
    const int aCol = (tid & 1) * 4;      // 0 or 4
    const int bRow = tid >> 5;           // 0..7
    const int bCol = (tid & 31) * 4;     // 0..124

    const int tr = (tid >> 4) * 8;       // row offset of 8x8 microtile
    const int tc = (tid & 15) * 8;       // col offset

    float acc[8][8];
#pragma unroll
    for (int i = 0; i < 8; i++)
#pragma unroll
        for (int j = 0; j < 8; j++) acc[i][j] = 0.f;

    for (int k0 = 0; k0 < K; k0 += 8) {
        float4 av = *(const float4*)(Ab + (size_t)aRow * K + k0 + aCol);
        As[aCol + 0][aRow] = av.x;
        As[aCol + 1][aRow] = av.y;
        As[aCol + 2][aRow] = av.z;
        As[aCol + 3][aRow] = av.w;
        float4 bv = *(const float4*)(Bb + (size_t)(k0 + bRow) * N + bCol);
        *(float4*)&Bs[bRow][bCol] = bv;
        __syncthreads();

#pragma unroll
        for (int kk = 0; kk < 8; kk++) {
            float ar[8], br[8];
            *(float4*)&ar[0] = *(float4*)&As[kk][tr];
            *(float4*)&ar[4] = *(float4*)&As[kk][tr + 4];
            *(float4*)&br[0] = *(float4*)&Bs[kk][tc];
            *(float4*)&br[4] = *(float4*)&Bs[kk][tc + 4];
#pragma unroll
            for (int i = 0; i < 8; i++)
#pragma unroll
                for (int j = 0; j < 8; j++) acc[i][j] += ar[i] * br[j];
        }
        __syncthreads();
    }

    float* Cb = C + (size_t)(brow * 128) * N + bcol * 128;
#pragma unroll
    for (int i = 0; i < 8; i++) {
#pragma unroll
        for (int j = 0; j < 8; j += 4) {
            float4 v = make_float4(acc[i][j], acc[i][j + 1], acc[i][j + 2], acc[i][j + 3]);
            *(float4*)(Cb + (size_t)(tr + i) * N + tc + j) = v;
        }
    }
}

// ---------------- dual (differential) causal flash attention ----------------
// One CTA handles 64 query rows of one (b,h). 256 threads, 16x16 layout,
// each thread owns a 4x4 tile of S/P/O. Online softmax for both score streams.
#define FS 68  // smem row stride (padding vs bank conflicts)

__global__ void __launch_bounds__(256) diff_flash(const float* __restrict__ qkv,
                                                  const float* __restrict__ lam_p,
                                                  float* __restrict__ attn_out) {
    extern __shared__ float sm[];
    float* Q1s = sm;
    float* Q2s = Q1s + 64 * FS;
    float* K1s = Q2s + 64 * FS;
    float* K2s = K1s + 64 * FS;
    float* Vs  = K2s + 64 * FS;
    float* P1s = Vs  + 64 * FS;
    float* P2s = P1s + 64 * FS;

    const int qt  = blockIdx.x;   // query tile (0..31)
    const int h   = blockIdx.y;
    const int b   = blockIdx.z;
    const int tid = threadIdx.x;
    const int tr  = tid >> 4;     // 0..15
    const int tc  = tid & 15;     // 0..15

    const int qrow0 = qt * 64;
    const float* base = qkv + (size_t)(b * TT) * NQKV + h * (5 * DD);

    // load Q1/Q2 tiles (64 rows x 64 dims each)
    for (int idx = tid; idx < 64 * 16; idx += 256) {
        int r = idx >> 4;
        int d = (idx & 15) * 4;
        const float* src = base + (size_t)(qrow0 + r) * NQKV + d;
        *(float4*)&Q1s[r * FS + d] = *(const float4*)(src + 0);
        *(float4*)&Q2s[r * FS + d] = *(const float4*)(src + 64);
    }

    float o1[4][4], o2[4][4];
    float m1[4], l1[4], m2[4], l2[4];
#pragma unroll
    for (int i = 0; i < 4; i++) {
        m1[i] = m2[i] = -1e30f;
        l1[i] = l2[i] = 0.f;
#pragma unroll
        for (int j = 0; j < 4; j++) { o1[i][j] = 0.f; o2[i][j] = 0.f; }
    }

    const float scale = 0.125f;  // 1/sqrt(64)

    for (int kt = 0; kt <= qt; ++kt) {
        __syncthreads();  // previous PV must be done before overwriting K/V
        for (int idx = tid; idx < 64 * 16; idx += 256) {
            int r = idx >> 4;
            int d = (idx & 15) * 4;
            const float* src = base + (size_t)(kt * 64 + r) * NQKV + d;
            *(float4*)&K1s[r * FS + d] = *(const float4*)(src + 128);
            *(float4*)&K2s[r * FS + d] = *(const float4*)(src + 192);
            *(float4*)&Vs [r * FS + d] = *(const float4*)(src + 256);
        }
        __syncthreads();

        float s1[4][4], s2[4][4];
#pragma unroll
        for (int i = 0; i < 4; i++)
#pragma unroll
            for (int j = 0; j < 4; j++) { s1[i][j] = 0.f; s2[i][j] = 0.f; }

        // S1 = Q1 K1^T
#pragma unroll 4
        for (int d = 0; d < 64; d += 4) {
            float4 qv[4], kv[4];
#pragma unroll
            for (int i = 0; i < 4; i++) qv[i] = *(float4*)&Q1s[(tr * 4 + i) * FS + d];
#pragma unroll
            for (int j = 0; j < 4; j++) kv[j] = *(float4*)&K1s[(tc * 4 + j) * FS + d];
#pragma unroll
            for (int i = 0; i < 4; i++)
#pragma unroll
                for (int j = 0; j < 4; j++)
                    s1[i][j] += qv[i].x * kv[j].x + qv[i].y * kv[j].y +
                                qv[i].z * kv[j].z + qv[i].w * kv[j].w;
        }
        // S2 = Q2 K2^T
#pragma unroll 4
        for (int d = 0; d < 64; d += 4) {
            float4 qv[4], kv[4];
#pragma unroll
            for (int i = 0; i < 4; i++) qv[i] = *(float4*)&Q2s[(tr * 4 + i) * FS + d];
#pragma unroll
            for (int j = 0; j < 4; j++) kv[j] = *(float4*)&K2s[(tc * 4 + j) * FS + d];
#pragma unroll
            for (int i = 0; i < 4; i++)
#pragma unroll
                for (int j = 0; j < 4; j++)
                    s2[i][j] += qv[i].x * kv[j].x + qv[i].y * kv[j].y +
                                qv[i].z * kv[j].z + qv[i].w * kv[j].w;
        }

        // scale + causal mask (only the diagonal tile needs masking)
        const bool diag = (kt == qt);
#pragma unroll
        for (int i = 0; i < 4; i++)
#pragma unroll
            for (int j = 0; j < 4; j++) {
                float msk = 0.f;
                if (diag && (tc * 4 + j) > (tr * 4 + i)) msk = -1e9f;
                s1[i][j] = s1[i][j] * scale + msk;
                s2[i][j] = s2[i][j] * scale + msk;
            }

        // online softmax update, both streams
#pragma unroll
        for (int i = 0; i < 4; i++) {
            // stream 1
            {
                float rmax = fmaxf(fmaxf(s1[i][0], s1[i][1]), fmaxf(s1[i][2], s1[i][3]));
#pragma unroll
                for (int off = 8; off; off >>= 1)
                    rmax = fmaxf(rmax, __shfl_xor_sync(0xffffffffu, rmax, off, 16));
                float mnew  = fmaxf(m1[i], rmax);
                float alpha = __expf(m1[i] - mnew);
                float4 p;
                p.x = __expf(s1[i][0] - mnew);
                p.y = __expf(s1[i][1] - mnew);
                p.z = __expf(s1[i][2] - mnew);
                p.w = __expf(s1[i][3] - mnew);
                *(float4*)&P1s[(tr * 4 + i) * FS + tc * 4] = p;
                float rsum = p.x + p.y + p.z + p.w;
#pragma unroll
                for (int off = 8; off; off >>= 1)
                    rsum += __shfl_xor_sync(0xffffffffu, rsum, off, 16);
                l1[i] = l1[i] * alpha + rsum;
                m1[i] = mnew;
#pragma unroll
                for (int j = 0; j < 4; j++) o1[i][j] *= alpha;
            }
            // stream 2
            {
                float rmax = fmaxf(fmaxf(s2[i][0], s2[i][1]), fmaxf(s2[i][2], s2[i][3]));
#pragma unroll
                for (int off = 8; off; off >>= 1)
                    rmax = fmaxf(rmax, __shfl_xor_sync(0xffffffffu, rmax, off, 16));
                float mnew  = fmaxf(m2[i], rmax);
                float alpha = __expf(m2[i] - mnew);
                float4 p;
                p.x = __expf(s2[i][0] - mnew);
                p.y = __expf(s2[i][1] - mnew);
                p.z = __expf(s2[i][2] - mnew);
                p.w = __expf(s2[i][3] - mnew);
                *(float4*)&P2s[(tr * 4 + i) * FS + tc * 4] = p;
                float rsum = p.x + p.y + p.z + p.w;
#pragma unroll
                for (int off = 8; off; off >>= 1)
                    rsum += __shfl_xor_sync(0xffffffffu, rsum, off, 16);
                l2[i] = l2[i] * alpha + rsum;
                m2[i] = mnew;
#pragma unroll
                for (int j = 0; j < 4; j++) o2[i][j] *= alpha;
            }
        }
        __syncthreads();

        // O += P * V for both streams (V loads shared)
#pragma unroll 2
        for (int c = 0; c < 64; c++) {
            float4 v = *(float4*)&Vs[c * FS + tc * 4];
            float p1a[4], p2a[4];
#pragma unroll
            for (int i = 0; i < 4; i++) {
                p1a[i] = P1s[(tr * 4 + i) * FS + c];
                p2a[i] = P2s[(tr * 4 + i) * FS + c];
            }
#pragma unroll
            for (int i = 0; i < 4; i++) {
                o1[i][0] += p1a[i] * v.x; o1[i][1] += p1a[i] * v.y;
                o1[i][2] += p1a[i] * v.z; o1[i][3] += p1a[i] * v.w;
                o2[i][0] += p2a[i] * v.x; o2[i][1] += p2a[i] * v.y;
                o2[i][2] += p2a[i] * v.z; o2[i][3] += p2a[i] * v.w;
            }
        }
    }

    // epilogue: out = O1/l1 - lam * O2/l2, write (B,T,H*D) layout
    float lamv = fminf(fmaxf(lam_p[h], 0.f), 1.f);
#pragma unroll
    for (int i = 0; i < 4; i++) {
        float inv1 = 1.f / l1[i];
        float inv2 = lamv / l2[i];
        float4 r;
        r.x = o1[i][0] * inv1 - o2[i][0] * inv2;
        r.y = o1[i][1] * inv1 - o2[i][1] * inv2;
        r.z = o1[i][2] * inv1 - o2[i][2] * inv2;
        r.w = o1[i][3] * inv1 - o2[i][3] * inv2;
        size_t row = (size_t)(b * TT + qrow0 + tr * 4 + i);
        *(float4*)&attn_out[row * DM + h * DD + tc * 4] = r;
    }
}

// ---------------- launch ----------------
extern "C" void kernel_launch(void* const* d_in, const int* in_sizes, int n_in,
                              void* d_out, int out_size) {
    const float* x    = (const float*)d_in[0];
    // d_in[1] = mask: causality is implemented directly
    const float* Wqkv = (const float*)d_in[2];
    const float* Wout = (const float*)d_in[3];
    const float* lam  = (const float*)d_in[4];
    float* out = (float*)d_out;

    float* qkv  = nullptr;
    float* attn = nullptr;
    cudaGetSymbolAddress((void**)&qkv,  g_qkv);
    cudaGetSymbolAddress((void**)&attn, g_attn);

    const int smem_bytes = 7 * 64 * FS * 4;  // 121856 B
    cudaFuncSetAttribute(diff_flash, cudaFuncAttributeMaxDynamicSharedMemorySize, smem_bytes);

    // 1) QKV projection: (4096 x 1024) @ (1024 x 5120)
    sgemm128<<<dim3(NQKV / 128, BT / 128), 256>>>(x, Wqkv, qkv, BT, NQKV, DM);

    // 2) dual causal flash attention
    diff_flash<<<dim3(TT / 64, HH, BB), 256, smem_bytes>>>(qkv, lam, attn);

    // 3) output projection: (4096 x 1024) @ (1024 x 1024)
    sgemm128<<<dim3(DM / 128, BT / 128), 256>>>(attn, Wout, out, BT, DM, DM);
}

// round 6
// speedup vs baseline: 1.1976x; 1.1976x over previous
#include <cuda_runtime.h>
#include <cuda_bf16.h>
#include <math.h>
#include <cstdint>

// Problem constants
#define BB 2
#define TT 2048
#define DM 1024
#define HH 16
#define DD 64
#define NQKV 5120     // H * 5 * D
#define BT  4096      // B * T
#define KE  3072      // split-K: [hi|hi|lo] x [hi|lo|hi]

// ---------------- scratch (no cudaMalloc allowed) ----------------
__device__ __align__(16) float g_qkv[(size_t)BT * NQKV];             // 83.9 MB
__device__ __align__(16) float g_attn[(size_t)BT * DM];              // 16.8 MB
__device__ __align__(16) __nv_bfloat16 g_Ab[(size_t)BT * KE];        // 25.2 MB
__device__ __align__(16) __nv_bfloat16 g_Bq[(size_t)NQKV * KE];      // 31.5 MB
__device__ __align__(16) __nv_bfloat16 g_Bo[(size_t)DM * KE];        // 6.3 MB

// ================= helpers (plain sm_103-safe PTX only) =================
__device__ __forceinline__ uint32_t smem_u32(const void* p) {
    uint32_t a;
    asm("{ .reg .u64 t; cvta.to.shared.u64 t, %1; cvt.u32.u64 %0, t; }" : "=r"(a) : "l"(p));
    return a;
}
#define CP16(smem, gptr) \
    asm volatile("cp.async.cg.shared.global [%0], [%1], 16;" :: "r"(smem), "l"(gptr) : "memory")
#define CP_COMMIT() asm volatile("cp.async.commit_group;" ::: "memory")
#define CP_WAIT(n)  asm volatile("cp.async.wait_group %0;" :: "n"(n) : "memory")
#define LDSM_X4(r0, r1, r2, r3, addr) \
    asm volatile("ldmatrix.sync.aligned.m8n8.x4.shared.b16 {%0,%1,%2,%3}, [%4];" \
                 : "=r"(r0), "=r"(r1), "=r"(r2), "=r"(r3) : "r"(addr))
#define MMA16816(c, a, b) \
    asm volatile("mma.sync.aligned.m16n8k16.row.col.f32.bf16.bf16.f32 " \
                 "{%0,%1,%2,%3}, {%4,%5,%6,%7}, {%8,%9}, {%0,%1,%2,%3};" \
                 : "+f"((c)[0]), "+f"((c)[1]), "+f"((c)[2]), "+f"((c)[3]) \
                 : "r"((a)[0]), "r"((a)[1]), "r"((a)[2]), "r"((a)[3]), \
                   "r"((b)[0]), "r"((b)[1]))

// ================= conversion kernels =================
// fp32 [M,1024] row-major -> bf16 [M,3072]: cols [0,1024)=hi [1024,2048)=hi [2048,3072)=lo
__global__ void __launch_bounds__(256) split_rows(const float* __restrict__ in,
                                                  __nv_bfloat16* __restrict__ out, int total) {
    int idx = blockIdx.x * 256 + threadIdx.x;
    if (idx >= total) return;
    int m = idx >> 10, k = idx & 1023;
    float v = in[idx];
    __nv_bfloat16 h = __float2bfloat16(v);
    __nv_bfloat16 l = __float2bfloat16(v - __bfloat162float(h));
    size_t rb = (size_t)m * KE;
    out[rb + k] = h;
    out[rb + 1024 + k] = h;
    out[rb + 2048 + k] = l;
}

// W fp32 [1024, N] -> bf16 [N, 3072] transposed: cols [0,1024)=hi [1024,2048)=lo [2048,3072)=hi
__global__ void __launch_bounds__(256) splitT(const float* __restrict__ W,
                                              __nv_bfloat16* __restrict__ out, int N) {
    __shared__ float smt[32][33];
    int n0 = blockIdx.x * 32, k0 = blockIdx.y * 32;
    int tx = threadIdx.x, ty = threadIdx.y;  // 32 x 8
#pragma unroll
    for (int i = 0; i < 4; i++)
        smt[ty * 4 + i][tx] = W[(size_t)(k0 + ty * 4 + i) * N + n0 + tx];
    __syncthreads();
#pragma unroll
    for (int i = 0; i < 4; i++) {
        int nn = ty * 4 + i;
        float v = smt[tx][nn];
        __nv_bfloat16 h = __float2bfloat16(v);
        __nv_bfloat16 l = __float2bfloat16(v - __bfloat162float(h));
        size_t rb = (size_t)(n0 + nn) * KE + k0 + tx;
        out[rb] = h;
        out[rb + 1024] = l;
        out[rb + 2048] = h;
    }
}

// ================= HMMA bf16 GEMM: C[M,N] = A[M,KE] @ B[N,KE]^T =================
// 128x128x64 CTA tile, 256 threads = 8 warps in 4(m) x 2(n), warp tile 32x64.
#define BKC 64
#define NK (KE / BKC)         // 48
#define ASTR 72               // smem row stride in bf16 (144B, 16B-multiple, conflict-free)
#define STAGE_HALF (128 * ASTR)            // bf16 elems per matrix per stage
#define STAGE_FULL (2 * STAGE_HALF)        // A + B
#define GEMM_SMEM (2 * STAGE_FULL * 2)     // bytes, double buffered = 73728

__global__ void __launch_bounds__(256) gemm_mma(const __nv_bfloat16* __restrict__ A,
                                                const __nv_bfloat16* __restrict__ B,
                                                float* __restrict__ C, int Ntot) {
    extern __shared__ __nv_bfloat16 smb[];
    const int tid = threadIdx.x;
    const int wid = tid >> 5;
    const int lane = tid & 31;
    const int m0 = blockIdx.y * 128;
    const int n0 = blockIdx.x * 128;
    const int wm = (wid >> 1) * 32;   // warp m offset in tile
    const int wn = (wid & 1) * 64;    // warp n offset in tile
    const uint32_t sbase = smem_u32(smb);

    // --- cp.async load mapping: thread -> (row, 32-col half) ---
    const int ldrow = tid >> 1;
    const int ldcol = (tid & 1) * 32;
    const __nv_bfloat16* Agp = A + (size_t)(m0 + ldrow) * KE + ldcol;
    const __nv_bfloat16* Bgp = B + (size_t)(n0 + ldrow) * KE + ldcol;
    const uint32_t st_off = (uint32_t)(ldrow * ASTR + ldcol) * 2;   // byte offset in stage

    // --- ldmatrix address offsets (bytes within a stage's A / B region) ---
    uint32_t aoff[2], boff[4];
#pragma unroll
    for (int mt = 0; mt < 2; mt++) {
        int row = wm + mt * 16 + (lane & 15);
        int col = (lane >> 4) * 8;
        aoff[mt] = (uint32_t)(row * ASTR + col) * 2;
    }
#pragma unroll
    for (int nt2 = 0; nt2 < 4; nt2++) {
        int n = wn + nt2 * 16 + ((lane >> 4) & 1) * 8 + (lane & 7);
        int k = ((lane >> 3) & 1) * 8;
        boff[nt2] = (uint32_t)(n * ASTR + k) * 2;
    }

    float acc[2][8][4];
#pragma unroll
    for (int mt = 0; mt < 2; mt++)
#pragma unroll
        for (int nt = 0; nt < 8; nt++)
#pragma unroll
            for (int j = 0; j < 4; j++) acc[mt][nt][j] = 0.f;

    // prologue: stage 0 <- chunk 0
    {
        uint32_t a_s = sbase + st_off;
        uint32_t b_s = a_s + STAGE_HALF * 2;
#pragma unroll
        for (int j = 0; j < 4; j++) {
            CP16(a_s + j * 16, Agp + j * 8);
            CP16(b_s + j * 16, Bgp + j * 8);
        }
        CP_COMMIT();
    }

    for (int i = 0; i < NK; i++) {
        const int buf = i & 1;
        if (i + 1 < NK) {
            const int nb = 1 - buf;
            const int k0 = (i + 1) * BKC;
            uint32_t a_s = sbase + (uint32_t)nb * STAGE_FULL * 2 + st_off;
            uint32_t b_s = a_s + STAGE_HALF * 2;
#pragma unroll
            for (int j = 0; j < 4; j++) {
                CP16(a_s + j * 16, Agp + k0 + j * 8);
                CP16(b_s + j * 16, Bgp + k0 + j * 8);
            }
            CP_COMMIT();
            CP_WAIT(1);
        } else {
            CP_WAIT(0);
        }
        __syncthreads();

        const uint32_t aSt = sbase + (uint32_t)buf * STAGE_FULL * 2;
        const uint32_t bSt = aSt + STAGE_HALF * 2;
#pragma unroll
        for (int ks = 0; ks < 4; ks++) {
            uint32_t afr[2][4], bfr[4][4];
#pragma unroll
            for (int mt = 0; mt < 2; mt++)
                LDSM_X4(afr[mt][0], afr[mt][1], afr[mt][2], afr[mt][3],
                        aSt + aoff[mt] + ks * 32);
#pragma unroll
            for (int nt2 = 0; nt2 < 4; nt2++)
                LDSM_X4(bfr[nt2][0], bfr[nt2][1], bfr[nt2][2], bfr[nt2][3],
                        bSt + boff[nt2] + ks * 32);
#pragma unroll
            for (int mt = 0; mt < 2; mt++)
#pragma unroll
                for (int nt2 = 0; nt2 < 4; nt2++) {
                    MMA16816(acc[mt][2 * nt2],     afr[mt], (&bfr[nt2][0]));
                    MMA16816(acc[mt][2 * nt2 + 1], afr[mt], (&bfr[nt2][2]));
                }
        }
        __syncthreads();
    }

    // epilogue: write fp32 C
#pragma unroll
    for (int mt = 0; mt < 2; mt++) {
        int r0 = m0 + wm + mt * 16 + (lane >> 2);
        int c0 = n0 + wn + (lane & 3) * 2;
        float* p0 = C + (size_t)r0 * Ntot + c0;
        float* p1 = C + (size_t)(r0 + 8) * Ntot + c0;
#pragma unroll
        for (int nt = 0; nt < 8; nt++) {
            *(float2*)(p0 + nt * 8) = make_float2(acc[mt][nt][0], acc[mt][nt][1]);
            *(float2*)(p1 + nt * 8) = make_float2(acc[mt][nt][2], acc[mt][nt][3]);
        }
    }
}

// ---------------- dual (differential) causal flash attention ----------------
#define FS 68  // smem row stride (padding vs bank conflicts)

__global__ void __launch_bounds__(256) diff_flash(const float* __restrict__ qkv,
                                                  const float* __restrict__ lam_p,
                                                  float* __restrict__ attn_out) {
    extern __shared__ float smf[];
    float* Q1s = smf;
    float* Q2s = Q1s + 64 * FS;
    float* K1s = Q2s + 64 * FS;
    float* K2s = K1s + 64 * FS;
    float* Vs  = K2s + 64 * FS;
    float* P1s = Vs  + 64 * FS;
    float* P2s = P1s + 64 * FS;

    const int qt  = blockIdx.x;
    const int h   = blockIdx.y;
    const int b   = blockIdx.z;
    const int tid = threadIdx.x;
    const int tr  = tid >> 4;
    const int tc  = tid & 15;

    const int qrow0 = qt * 64;
    const float* base = qkv + (size_t)(b * TT) * NQKV + h * (5 * DD);

    for (int idx = tid; idx < 64 * 16; idx += 256) {
        int r = idx >> 4;
        int d = (idx & 15) * 4;
        const float* src = base + (size_t)(qrow0 + r) * NQKV + d;
        *(float4*)&Q1s[r * FS + d] = *(const float4*)(src + 0);
        *(float4*)&Q2s[r * FS + d] = *(const float4*)(src + 64);
    }

    float o1[4][4], o2[4][4];
    float m1[4], l1[4], m2[4], l2[4];
#pragma unroll
    for (int i = 0; i < 4; i++) {
        m1[i] = m2[i] = -1e30f;
        l1[i] = l2[i] = 0.f;
#pragma unroll
        for (int j = 0; j < 4; j++) { o1[i][j] = 0.f; o2[i][j] = 0.f; }
    }

    const float scale = 0.125f;

    for (int kt = 0; kt <= qt; ++kt) {
        __syncthreads();
        for (int idx = tid; idx < 64 * 16; idx += 256) {
            int r = idx >> 4;
            int d = (idx & 15) * 4;
            const float* src = base + (size_t)(kt * 64 + r) * NQKV + d;
            *(float4*)&K1s[r * FS + d] = *(const float4*)(src + 128);
            *(float4*)&K2s[r * FS + d] = *(const float4*)(src + 192);
            *(float4*)&Vs [r * FS + d] = *(const float4*)(src + 256);
        }
        __syncthreads();

        float s1[4][4], s2[4][4];
#pragma unroll
        for (int i = 0; i < 4; i++)
#pragma unroll
            for (int j = 0; j < 4; j++) { s1[i][j] = 0.f; s2[i][j] = 0.f; }

#pragma unroll 4
        for (int d = 0; d < 64; d += 4) {
            float4 qv[4], kv[4];
#pragma unroll
            for (int i = 0; i < 4; i++) qv[i] = *(float4*)&Q1s[(tr * 4 + i) * FS + d];
#pragma unroll
            for (int j = 0; j < 4; j++) kv[j] = *(float4*)&K1s[(tc * 4 + j) * FS + d];
#pragma unroll
            for (int i = 0; i < 4; i++)
#pragma unroll
                for (int j = 0; j < 4; j++)
                    s1[i][j] += qv[i].x * kv[j].x + qv[i].y * kv[j].y +
                                qv[i].z * kv[j].z + qv[i].w * kv[j].w;
        }
#pragma unroll 4
        for (int d = 0; d < 64; d += 4) {
            float4 qv[4], kv[4];
#pragma unroll
            for (int i = 0; i < 4; i++) qv[i] = *(float4*)&Q2s[(tr * 4 + i) * FS + d];
#pragma unroll
            for (int j = 0; j < 4; j++) kv[j] = *(float4*)&K2s[(tc * 4 + j) * FS + d];
#pragma unroll
            for (int i = 0; i < 4; i++)
#pragma unroll
                for (int j = 0; j < 4; j++)
                    s2[i][j] += qv[i].x * kv[j].x + qv[i].y * kv[j].y +
                                qv[i].z * kv[j].z + qv[i].w * kv[j].w;
        }

        const bool diag = (kt == qt);
#pragma unroll
        for (int i = 0; i < 4; i++)
#pragma unroll
            for (int j = 0; j < 4; j++) {
                float msk = 0.f;
                if (diag && (tc * 4 + j) > (tr * 4 + i)) msk = -1e9f;
                s1[i][j] = s1[i][j] * scale + msk;
                s2[i][j] = s2[i][j] * scale + msk;
            }

#pragma unroll
        for (int i = 0; i < 4; i++) {
            {
                float rmax = fmaxf(fmaxf(s1[i][0], s1[i][1]), fmaxf(s1[i][2], s1[i][3]));
#pragma unroll
                for (int off = 8; off; off >>= 1)
                    rmax = fmaxf(rmax, __shfl_xor_sync(0xffffffffu, rmax, off, 16));
                float mnew  = fmaxf(m1[i], rmax);
                float alpha = __expf(m1[i] - mnew);
                float4 p;
                p.x = __expf(s1[i][0] - mnew);
                p.y = __expf(s1[i][1] - mnew);
                p.z = __expf(s1[i][2] - mnew);
                p.w = __expf(s1[i][3] - mnew);
                *(float4*)&P1s[(tr * 4 + i) * FS + tc * 4] = p;
                float rsum = p.x + p.y + p.z + p.w;
#pragma unroll
                for (int off = 8; off; off >>= 1)
                    rsum += __shfl_xor_sync(0xffffffffu, rsum, off, 16);
                l1[i] = l1[i] * alpha + rsum;
                m1[i] = mnew;
#pragma unroll
                for (int j = 0; j < 4; j++) o1[i][j] *= alpha;
            }
            {
                float rmax = fmaxf(fmaxf(s2[i][0], s2[i][1]), fmaxf(s2[i][2], s2[i][3]));
#pragma unroll
                for (int off = 8; off; off >>= 1)
                    rmax = fmaxf(rmax, __shfl_xor_sync(0xffffffffu, rmax, off, 16));
                float mnew  = fmaxf(m2[i], rmax);
                float alpha = __expf(m2[i] - mnew);
                float4 p;
                p.x = __expf(s2[i][0] - mnew);
                p.y = __expf(s2[i][1] - mnew);
                p.z = __expf(s2[i][2] - mnew);
                p.w = __expf(s2[i][3] - mnew);
                *(float4*)&P2s[(tr * 4 + i) * FS + tc * 4] = p;
                float rsum = p.x + p.y + p.z + p.w;
#pragma unroll
                for (int off = 8; off; off >>= 1)
                    rsum += __shfl_xor_sync(0xffffffffu, rsum, off, 16);
                l2[i] = l2[i] * alpha + rsum;
                m2[i] = mnew;
#pragma unroll
                for (int j = 0; j < 4; j++) o2[i][j] *= alpha;
            }
        }
        __syncthreads();

#pragma unroll 2
        for (int c = 0; c < 64; c++) {
            float4 v = *(float4*)&Vs[c * FS + tc * 4];
            float p1a[4], p2a[4];
#pragma unroll
            for (int i = 0; i < 4; i++) {
                p1a[i] = P1s[(tr * 4 + i) * FS + c];
                p2a[i] = P2s[(tr * 4 + i) * FS + c];
            }
#pragma unroll
            for (int i = 0; i < 4; i++) {
                o1[i][0] += p1a[i] * v.x; o1[i][1] += p1a[i] * v.y;
                o1[i][2] += p1a[i] * v.z; o1[i][3] += p1a[i] * v.w;
                o2[i][0] += p2a[i] * v.x; o2[i][1] += p2a[i] * v.y;
                o2[i][2] += p2a[i] * v.z; o2[i][3] += p2a[i] * v.w;
            }
        }
    }

    float lamv = fminf(fmaxf(lam_p[h], 0.f), 1.f);
#pragma unroll
    for (int i = 0; i < 4; i++) {
        float inv1 = 1.f / l1[i];
        float inv2 = lamv / l2[i];
        float4 r;
        r.x = o1[i][0] * inv1 - o2[i][0] * inv2;
        r.y = o1[i][1] * inv1 - o2[i][1] * inv2;
        r.z = o1[i][2] * inv1 - o2[i][2] * inv2;
        r.w = o1[i][3] * inv1 - o2[i][3] * inv2;
        size_t row = (size_t)(b * TT + qrow0 + tr * 4 + i);
        *(float4*)&attn_out[row * DM + h * DD + tc * 4] = r;
    }
}

// ---------------- launch ----------------
extern "C" void kernel_launch(void* const* d_in, const int* in_sizes, int n_in,
                              void* d_out, int out_size) {
    const float* x    = (const float*)d_in[0];
    const float* Wqkv = (const float*)d_in[2];
    const float* Wout = (const float*)d_in[3];
    const float* lam  = (const float*)d_in[4];
    float* out = (float*)d_out;

    float *qkv = nullptr, *attn = nullptr;
    __nv_bfloat16 *Ab = nullptr, *Bq = nullptr, *Bo = nullptr;
    cudaGetSymbolAddress((void**)&qkv,  g_qkv);
    cudaGetSymbolAddress((void**)&attn, g_attn);
    cudaGetSymbolAddress((void**)&Ab,   g_Ab);
    cudaGetSymbolAddress((void**)&Bq,   g_Bq);
    cudaGetSymbolAddress((void**)&Bo,   g_Bo);

    const int fl_smem = 7 * 64 * FS * 4;
    cudaFuncSetAttribute(diff_flash, cudaFuncAttributeMaxDynamicSharedMemorySize, fl_smem);
    cudaFuncSetAttribute(gemm_mma, cudaFuncAttributeMaxDynamicSharedMemorySize, GEMM_SMEM);

    // weight + input split/transpose conversions
    splitT<<<dim3(NQKV / 32, DM / 32), dim3(32, 8)>>>(Wqkv, Bq, NQKV);
    splitT<<<dim3(DM / 32, DM / 32), dim3(32, 8)>>>(Wout, Bo, DM);
    split_rows<<<(BT * DM + 255) / 256, 256>>>(x, Ab, BT * DM);

    // 1) QKV projection on tensor cores (HMMA): (4096 x 3072) @ (3072 x 5120)
    gemm_mma<<<dim3(NQKV / 128, BT / 128), 256, GEMM_SMEM>>>(Ab, Bq, qkv, NQKV);

    // 2) dual causal flash attention (fp32)
    diff_flash<<<dim3(TT / 64, HH, BB), 256, fl_smem>>>(qkv, lam, attn);

    // 3) output projection on tensor cores (HMMA)
    split_rows<<<(BT * DM + 255) / 256, 256>>>(attn, Ab, BT * DM);
    gemm_mma<<<dim3(DM / 128, BT / 128), 256, GEMM_SMEM>>>(Ab, Bo, out, DM);
}

// round 7
// speedup vs baseline: 2.6720x; 2.2311x over previous
#include <cuda_runtime.h>
#include <cuda_bf16.h>
#include <math.h>
#include <cstdint>

// Problem constants
#define BB 2
#define TT 2048
#define DM 1024
#define HH 16
#define DD 64
#define NQKV 5120     // H * 5 * D
#define BT  4096      // B * T
#define KE  3072      // split-K: [hi|hi|lo] x [hi|lo|hi]

// ---------------- scratch (no cudaMalloc allowed) ----------------
__device__ __align__(16) float g_qkv[(size_t)BT * NQKV];               // 83.9 MB
__device__ __align__(16) __nv_bfloat16 g_Ab[(size_t)BT * KE];          // 25.2 MB
__device__ __align__(16) __nv_bfloat16 g_Bq[(size_t)NQKV * KE];        // 31.5 MB
__device__ __align__(16) __nv_bfloat16 g_Bo[(size_t)DM * KE];          // 6.3 MB
// flash operands: [bh][t][hi(64)|lo(64)] and V^T [bh][d][hi plane 2048 | lo plane 2048]
__device__ __align__(16) __nv_bfloat16 g_Q1f[(size_t)BB * HH * TT * 128];
__device__ __align__(16) __nv_bfloat16 g_Q2f[(size_t)BB * HH * TT * 128];
__device__ __align__(16) __nv_bfloat16 g_K1f[(size_t)BB * HH * TT * 128];
__device__ __align__(16) __nv_bfloat16 g_K2f[(size_t)BB * HH * TT * 128];
__device__ __align__(16) __nv_bfloat16 g_Vt [(size_t)BB * HH * DD * (2 * TT)];

// ================= helpers (plain sm_103-safe PTX only) =================
__device__ __forceinline__ uint32_t smem_u32(const void* p) {
    uint32_t a;
    asm("{ .reg .u64 t; cvta.to.shared.u64 t, %1; cvt.u32.u64 %0, t; }" : "=r"(a) : "l"(p));
    return a;
}
#define CP16(smem, gptr) \
    asm volatile("cp.async.cg.shared.global [%0], [%1], 16;" :: "r"(smem), "l"(gptr) : "memory")
#define CP_COMMIT() asm volatile("cp.async.commit_group;" ::: "memory")
#define CP_WAIT(n)  asm volatile("cp.async.wait_group %0;" :: "n"(n) : "memory")
#define LDSM_X4(r0, r1, r2, r3, addr) \
    asm volatile("ldmatrix.sync.aligned.m8n8.x4.shared.b16 {%0,%1,%2,%3}, [%4];" \
                 : "=r"(r0), "=r"(r1), "=r"(r2), "=r"(r3) : "r"(addr))
#define MMA16816(c, a, b) \
    asm volatile("mma.sync.aligned.m16n8k16.row.col.f32.bf16.bf16.f32 " \
                 "{%0,%1,%2,%3}, {%4,%5,%6,%7}, {%8,%9}, {%0,%1,%2,%3};" \
                 : "+f"((c)[0]), "+f"((c)[1]), "+f"((c)[2]), "+f"((c)[3]) \
                 : "r"((a)[0]), "r"((a)[1]), "r"((a)[2]), "r"((a)[3]), \
                   "r"((b)[0]), "r"((b)[1]))

__device__ __forceinline__ uint32_t packbf(float lo, float hi) {
    __nv_bfloat162 t = __floats2bfloat162_rn(lo, hi);
    return *(uint32_t*)&t;
}

// ================= conversion kernels =================
// fp32 [M,1024] row-major -> bf16 [M,3072]: cols [0,1024)=hi [1024,2048)=hi [2048,3072)=lo
__global__ void __launch_bounds__(256) split_rows(const float* __restrict__ in,
                                                  __nv_bfloat16* __restrict__ out, int total) {
    int idx = blockIdx.x * 256 + threadIdx.x;
    if (idx >= total) return;
    int m = idx >> 10, k = idx & 1023;
    float v = in[idx];
    __nv_bfloat16 h = __float2bfloat16(v);
    __nv_bfloat16 l = __float2bfloat16(v - __bfloat162float(h));
    size_t rb = (size_t)m * KE;
    out[rb + k] = h;
    out[rb + 1024 + k] = h;
    out[rb + 2048 + k] = l;
}

// W fp32 [1024, N] -> bf16 [N, 3072] transposed: cols [0,1024)=hi [1024,2048)=lo [2048,3072)=hi
__global__ void __launch_bounds__(256) splitT(const float* __restrict__ W,
                                              __nv_bfloat16* __restrict__ out, int N) {
    __shared__ float smt[32][33];
    int n0 = blockIdx.x * 32, k0 = blockIdx.y * 32;
    int tx = threadIdx.x, ty = threadIdx.y;  // 32 x 8
#pragma unroll
    for (int i = 0; i < 4; i++)
        smt[ty * 4 + i][tx] = W[(size_t)(k0 + ty * 4 + i) * N + n0 + tx];
    __syncthreads();
#pragma unroll
    for (int i = 0; i < 4; i++) {
        int nn = ty * 4 + i;
        float v = smt[tx][nn];
        __nv_bfloat16 h = __float2bfloat16(v);
        __nv_bfloat16 l = __float2bfloat16(v - __bfloat162float(h));
        size_t rb = (size_t)(n0 + nn) * KE + k0 + tx;
        out[rb] = h;
        out[rb + 1024] = l;
        out[rb + 2048] = h;
    }
}

// g_qkv fp32 -> Q1/Q2/K1/K2 bf16 [bh][t][hi|lo]
__global__ void __launch_bounds__(256) qkv_split(const float* __restrict__ qkv,
                                                 __nv_bfloat16* __restrict__ Q1,
                                                 __nv_bfloat16* __restrict__ Q2,
                                                 __nv_bfloat16* __restrict__ K1,
                                                 __nv_bfloat16* __restrict__ K2) {
    int idx = blockIdx.x * 256 + threadIdx.x;           // over bh*T*64
    if (idx >= BB * HH * TT * DD) return;
    int d = idx & 63;
    int t = (idx >> 6) & (TT - 1);
    int bh = idx >> 17;
    int b = bh >> 4, h = bh & 15;
    const float* src = qkv + (size_t)(b * TT + t) * NQKV + h * 320 + d;
    size_t dst = ((size_t)bh * TT + t) * 128 + d;
    float v;
    __nv_bfloat16 hi;
    v = src[0];   hi = __float2bfloat16(v); Q1[dst] = hi; Q1[dst + 64] = __float2bfloat16(v - __bfloat162float(hi));
    v = src[64];  hi = __float2bfloat16(v); Q2[dst] = hi; Q2[dst + 64] = __float2bfloat16(v - __bfloat162float(hi));
    v = src[128]; hi = __float2bfloat16(v); K1[dst] = hi; K1[dst + 64] = __float2bfloat16(v - __bfloat162float(hi));
    v = src[192]; hi = __float2bfloat16(v); K2[dst] = hi; K2[dst + 64] = __float2bfloat16(v - __bfloat162float(hi));
}

// V fp32 [t, d] -> V^T bf16 [bh][d][hi plane t | lo plane t]
__global__ void __launch_bounds__(256) v_transpose(const float* __restrict__ qkv,
                                                   __nv_bfloat16* __restrict__ Vt) {
    __shared__ float tile[64][65];
    int t0 = blockIdx.x * 64;
    int bh = blockIdx.y;
    int b = bh >> 4, h = bh & 15;
    int c = threadIdx.x & 63, r4 = threadIdx.x >> 6;
#pragma unroll
    for (int rr = r4; rr < 64; rr += 4)
        tile[rr][c] = qkv[(size_t)(b * TT + t0 + rr) * NQKV + h * 320 + 256 + c];
    __syncthreads();
#pragma unroll
    for (int dd = r4; dd < 64; dd += 4) {
        float v = tile[c][dd];
        __nv_bfloat16 hi = __float2bfloat16(v);
        size_t base = ((size_t)bh * DD + dd) * (2 * TT) + t0 + c;
        Vt[base] = hi;
        Vt[base + TT] = __float2bfloat16(v - __bfloat162float(hi));
    }
}

// ================= HMMA bf16 GEMM: C[M,N] = A[M,KE] @ B[N,KE]^T =================
#define BKC 64
#define NK (KE / BKC)         // 48
#define ASTR 72
#define STAGE_HALF (128 * ASTR)
#define STAGE_FULL (2 * STAGE_HALF)
#define GEMM_SMEM (2 * STAGE_FULL * 2)

__global__ void __launch_bounds__(256) gemm_mma(const __nv_bfloat16* __restrict__ A,
                                                const __nv_bfloat16* __restrict__ B,
                                                float* __restrict__ C, int Ntot) {
    extern __shared__ __nv_bfloat16 smb[];
    const int tid = threadIdx.x;
    const int wid = tid >> 5;
    const int lane = tid & 31;
    const int m0 = blockIdx.y * 128;
    const int n0 = blockIdx.x * 128;
    const int wm = (wid >> 1) * 32;
    const int wn = (wid & 1) * 64;
    const uint32_t sbase = smem_u32(smb);

    const int ldrow = tid >> 1;
    const int ldcol = (tid & 1) * 32;
    const __nv_bfloat16* Agp = A + (size_t)(m0 + ldrow) * KE + ldcol;
    const __nv_bfloat16* Bgp = B + (size_t)(n0 + ldrow) * KE + ldcol;
    const uint32_t st_off = (uint32_t)(ldrow * ASTR + ldcol) * 2;

    uint32_t aoff[2], boff[4];
#pragma unroll
    for (int mt = 0; mt < 2; mt++) {
        int row = wm + mt * 16 + (lane & 15);
        int col = (lane >> 4) * 8;
        aoff[mt] = (uint32_t)(row * ASTR + col) * 2;
    }
#pragma unroll
    for (int nt2 = 0; nt2 < 4; nt2++) {
        int n = wn + nt2 * 16 + ((lane >> 4) & 1) * 8 + (lane & 7);
        int k = ((lane >> 3) & 1) * 8;
        boff[nt2] = (uint32_t)(n * ASTR + k) * 2;
    }

    float acc[2][8][4];
#pragma unroll
    for (int mt = 0; mt < 2; mt++)
#pragma unroll
        for (int nt = 0; nt < 8; nt++)
#pragma unroll
            for (int j = 0; j < 4; j++) acc[mt][nt][j] = 0.f;

    {
        uint32_t a_s = sbase + st_off;
        uint32_t b_s = a_s + STAGE_HALF * 2;
#pragma unroll
        for (int j = 0; j < 4; j++) {
            CP16(a_s + j * 16, Agp + j * 8);
            CP16(b_s + j * 16, Bgp + j * 8);
        }
        CP_COMMIT();
    }

    for (int i = 0; i < NK; i++) {
        const int buf = i & 1;
        if (i + 1 < NK) {
            const int nb = 1 - buf;
            const int k0 = (i + 1) * BKC;
            uint32_t a_s = sbase + (uint32_t)nb * STAGE_FULL * 2 + st_off;
            uint32_t b_s = a_s + STAGE_HALF * 2;
#pragma unroll
            for (int j = 0; j < 4; j++) {
                CP16(a_s + j * 16, Agp + k0 + j * 8);
                CP16(b_s + j * 16, Bgp + k0 + j * 8);
            }
            CP_COMMIT();
            CP_WAIT(1);
        } else {
            CP_WAIT(0);
        }
        __syncthreads();

        const uint32_t aSt = sbase + (uint32_t)buf * STAGE_FULL * 2;
        const uint32_t bSt = aSt + STAGE_HALF * 2;
#pragma unroll
        for (int ks = 0; ks < 4; ks++) {
            uint32_t afr[2][4], bfr[4][4];
#pragma unroll
            for (int mt = 0; mt < 2; mt++)
                LDSM_X4(afr[mt][0], afr[mt][1], afr[mt][2], afr[mt][3],
                        aSt + aoff[mt] + ks * 32);
#pragma unroll
            for (int nt2 = 0; nt2 < 4; nt2++)
                LDSM_X4(bfr[nt2][0], bfr[nt2][1], bfr[nt2][2], bfr[nt2][3],
                        bSt + boff[nt2] + ks * 32);
#pragma unroll
            for (int mt = 0; mt < 2; mt++)
#pragma unroll
                for (int nt2 = 0; nt2 < 4; nt2++) {
                    MMA16816(acc[mt][2 * nt2],     afr[mt], (&bfr[nt2][0]));
                    MMA16816(acc[mt][2 * nt2 + 1], afr[mt], (&bfr[nt2][2]));
                }
        }
        __syncthreads();
    }

#pragma unroll
    for (int mt = 0; mt < 2; mt++) {
        int r0 = m0 + wm + mt * 16 + (lane >> 2);
        int c0 = n0 + wn + (lane & 3) * 2;
        float* p0 = C + (size_t)r0 * Ntot + c0;
        float* p1 = C + (size_t)(r0 + 8) * Ntot + c0;
#pragma unroll
        for (int nt = 0; nt < 8; nt++) {
            *(float2*)(p0 + nt * 8) = make_float2(acc[mt][nt][0], acc[mt][nt][1]);
            *(float2*)(p1 + nt * 8) = make_float2(acc[mt][nt][2], acc[mt][nt][3]);
        }
    }
}

// ================= HMMA dual flash attention =================
// CTA: 128 q-rows of one (b,h); 8 warps, warp = m16. kv tiles of 64, double-buffered.
#define QSTR 136                      // bf16 row stride (272B, conflict-free)
#define FL_Q1 0
#define FL_Q2 (128 * QSTR)
#define FL_ST0 (2 * 128 * QSTR)
#define FL_KV (64 * QSTR)             // one tensor in a stage
#define FL_STAGE (3 * FL_KV)          // K1 | K2 | Vt
#define FL_SMEM_BYTES ((2 * 128 * QSTR + 2 * FL_STAGE) * 2)   // 174080

__device__ __forceinline__ void fl_load_kv(uint32_t sb, int st, int kt, int tid,
                                           const __nv_bfloat16* K1g,
                                           const __nv_bfloat16* K2g,
                                           const __nv_bfloat16* Vg) {
    int r = tid >> 2, qd = tid & 3;
    uint32_t base = sb + (uint32_t)(FL_ST0 + st * FL_STAGE) * 2;
    uint32_t o = (uint32_t)(r * QSTR + qd * 32) * 2;
    const __nv_bfloat16* k1 = K1g + (size_t)(kt * 64 + r) * 128 + qd * 32;
    const __nv_bfloat16* k2 = K2g + (size_t)(kt * 64 + r) * 128 + qd * 32;
    const __nv_bfloat16* vv = Vg + (size_t)r * (2 * TT) + ((qd >> 1) ? TT : 0) + kt * 64 + (qd & 1) * 32;
#pragma unroll
    for (int j = 0; j < 4; j++) {
        CP16(base + o + j * 16, k1 + j * 8);
        CP16(base + FL_KV * 2 + o + j * 16, k2 + j * 8);
        CP16(base + 2 * FL_KV * 2 + o + j * 16, vv + j * 8);
    }
}

// one stream (S = Q K^T split, online softmax, O += P V split)
__device__ __forceinline__ void fl_stream(uint32_t a_addr, uint32_t kstage, uint32_t vstage,
                                          uint32_t b_lane_b, int kt, bool need_mask,
                                          int row_g0, int lane,
                                          float O[8][4], float* mst, float* lst) {
    float acc[8][4];
#pragma unroll
    for (int nb = 0; nb < 8; nb++)
#pragma unroll
        for (int j = 0; j < 4; j++) acc[nb][j] = 0.f;

    // S = Q K^T with 3-combo split: (hi,hi) (hi,lo) (lo,hi); k16 steps
    const int qoffs[12] = {0,16,32,48, 0,16,32,48, 64,80,96,112};
    const int koffs[12] = {0,16,32,48, 64,80,96,112, 0,16,32,48};
#pragma unroll
    for (int s = 0; s < 12; s++) {
        uint32_t af[4];
        LDSM_X4(af[0], af[1], af[2], af[3], a_addr + qoffs[s] * 2);
#pragma unroll
        for (int nt2 = 0; nt2 < 4; nt2++) {
            uint32_t bf[4];
            LDSM_X4(bf[0], bf[1], bf[2], bf[3],
                    kstage + b_lane_b + (uint32_t)(nt2 * 16 * QSTR + koffs[s]) * 2);
            MMA16816(acc[2 * nt2],     af, (&bf[0]));
            MMA16816(acc[2 * nt2 + 1], af, (&bf[2]));
        }
    }

    // scale + causal mask
#pragma unroll
    for (int nb = 0; nb < 8; nb++)
#pragma unroll
        for (int j = 0; j < 4; j++) {
            float v = acc[nb][j] * 0.125f;
            if (need_mask) {
                int col = kt * 64 + nb * 8 + 2 * (lane & 3) + (j & 1);
                int row = row_g0 + ((j >> 1) << 3);
                if (col > row) v = -1e30f;
            }
            acc[nb][j] = v;
        }

    // online softmax (rows r and r+8)
    float mx0 = -1e30f, mx1 = -1e30f;
#pragma unroll
    for (int nb = 0; nb < 8; nb++) {
        mx0 = fmaxf(mx0, fmaxf(acc[nb][0], acc[nb][1]));
        mx1 = fmaxf(mx1, fmaxf(acc[nb][2], acc[nb][3]));
    }
    mx0 = fmaxf(mx0, __shfl_xor_sync(0xffffffffu, mx0, 1));
    mx0 = fmaxf(mx0, __shfl_xor_sync(0xffffffffu, mx0, 2));
    mx1 = fmaxf(mx1, __shfl_xor_sync(0xffffffffu, mx1, 1));
    mx1 = fmaxf(mx1, __shfl_xor_sync(0xffffffffu, mx1, 2));
    float mn0 = fmaxf(mst[0], mx0), mn1 = fmaxf(mst[1], mx1);
    float al0 = __expf(mst[0] - mn0), al1 = __expf(mst[1] - mn1);
    float s0 = 0.f, s1 = 0.f;
#pragma unroll
    for (int nb = 0; nb < 8; nb++) {
        acc[nb][0] = __expf(acc[nb][0] - mn0);
        acc[nb][1] = __expf(acc[nb][1] - mn0);
        acc[nb][2] = __expf(acc[nb][2] - mn1);
        acc[nb][3] = __expf(acc[nb][3] - mn1);
        s0 += acc[nb][0] + acc[nb][1];
        s1 += acc[nb][2] + acc[nb][3];
    }
    s0 += __shfl_xor_sync(0xffffffffu, s0, 1);
    s0 += __shfl_xor_sync(0xffffffffu, s0, 2);
    s1 += __shfl_xor_sync(0xffffffffu, s1, 1);
    s1 += __shfl_xor_sync(0xffffffffu, s1, 2);
    lst[0] = lst[0] * al0 + s0;
    lst[1] = lst[1] * al1 + s1;
    mst[0] = mn0;
    mst[1] = mn1;
#pragma unroll
    for (int nb = 0; nb < 8; nb++) {
        O[nb][0] *= al0; O[nb][1] *= al0;
        O[nb][2] *= al1; O[nb][3] *= al1;
    }

    // O += P V (register-direct P fragments, split: Ph*Vhi + Pl*Vhi + Ph*Vlo)
#pragma unroll
    for (int s = 0; s < 4; s++) {
        uint32_t ah[4], al_[4];
        ah[0] = packbf(acc[2 * s][0],     acc[2 * s][1]);
        ah[1] = packbf(acc[2 * s][2],     acc[2 * s][3]);
        ah[2] = packbf(acc[2 * s + 1][0], acc[2 * s + 1][1]);
        ah[3] = packbf(acc[2 * s + 1][2], acc[2 * s + 1][3]);
#pragma unroll
        for (int q = 0; q < 4; q++) {
            __nv_bfloat162 hv = *(__nv_bfloat162*)&ah[q];
            float2 hf = __bfloat1622float2(hv);
            int nb = 2 * s + (q >> 1);
            int j0 = (q & 1) * 2;
            al_[q] = packbf(acc[nb][j0] - hf.x, acc[nb][j0 + 1] - hf.y);
        }
#pragma unroll
        for (int nt2 = 0; nt2 < 4; nt2++) {
            uint32_t bh_[4], bl_[4];
            uint32_t vb = vstage + b_lane_b + (uint32_t)(nt2 * 16 * QSTR) * 2;
            LDSM_X4(bh_[0], bh_[1], bh_[2], bh_[3], vb + (uint32_t)(s * 16) * 2);
            LDSM_X4(bl_[0], bl_[1], bl_[2], bl_[3], vb + (uint32_t)(64 + s * 16) * 2);
            MMA16816(O[2 * nt2],     ah,  (&bh_[0]));
            MMA16816(O[2 * nt2 + 1], ah,  (&bh_[2]));
            MMA16816(O[2 * nt2],     al_, (&bh_[0]));
            MMA16816(O[2 * nt2 + 1], al_, (&bh_[2]));
            MMA16816(O[2 * nt2],     ah,  (&bl_[0]));
            MMA16816(O[2 * nt2 + 1], ah,  (&bl_[2]));
        }
    }
}

__global__ void __launch_bounds__(256) flash_mma(
    const __nv_bfloat16* __restrict__ Q1f, const __nv_bfloat16* __restrict__ Q2f,
    const __nv_bfloat16* __restrict__ K1f, const __nv_bfloat16* __restrict__ K2f,
    const __nv_bfloat16* __restrict__ Vtg, const float* __restrict__ lam_p,
    __nv_bfloat16* __restrict__ Ab) {
    extern __shared__ __nv_bfloat16 sfb[];
    const uint32_t sb = smem_u32(sfb);
    const int tid = threadIdx.x, wid = tid >> 5, lane = tid & 31;
    const int qrev = gridDim.x - 1 - blockIdx.x;    // heavy CTAs first
    const int q0 = qrev * 128;
    const int h = blockIdx.y, b = blockIdx.z;
    const int bh = b * HH + h;
    const int nkv = 2 * qrev + 2;

    const __nv_bfloat16* Q1g = Q1f + ((size_t)bh * TT + q0) * 128;
    const __nv_bfloat16* Q2g = Q2f + ((size_t)bh * TT + q0) * 128;
    const __nv_bfloat16* K1g = K1f + (size_t)bh * TT * 128;
    const __nv_bfloat16* K2g = K2f + (size_t)bh * TT * 128;
    const __nv_bfloat16* Vg  = Vtg + (size_t)bh * DD * (2 * TT);

    // Q tiles via cp.async
    {
        int row = tid >> 1, hf = (tid & 1) * 64;
        uint32_t d1 = sb + (uint32_t)(FL_Q1 + row * QSTR + hf) * 2;
        uint32_t d2 = sb + (uint32_t)(FL_Q2 + row * QSTR + hf) * 2;
        const __nv_bfloat16* s1 = Q1g + row * 128 + hf;
        const __nv_bfloat16* s2 = Q2g + row * 128 + hf;
#pragma unroll
        for (int j = 0; j < 8; j++) { CP16(d1 + j * 16, s1 + j * 8); CP16(d2 + j * 16, s2 + j * 8); }
    }
    fl_load_kv(sb, 0, 0, tid, K1g, K2g, Vg);
    CP_COMMIT();

    float O1[8][4], O2[8][4];
#pragma unroll
    for (int nb = 0; nb < 8; nb++)
#pragma unroll
        for (int j = 0; j < 4; j++) { O1[nb][j] = 0.f; O2[nb][j] = 0.f; }
    float m1[2] = {-1e30f, -1e30f}, l1[2] = {0.f, 0.f};
    float m2[2] = {-1e30f, -1e30f}, l2[2] = {0.f, 0.f};

    const int row_g0 = q0 + wid * 16 + (lane >> 2);
    const uint32_t a_lane = (uint32_t)((lane & 15) * QSTR + (lane >> 4) * 8) * 2;
    const uint32_t aQ1 = sb + (uint32_t)(FL_Q1 + wid * 16 * QSTR) * 2 + a_lane;
    const uint32_t aQ2 = sb + (uint32_t)(FL_Q2 + wid * 16 * QSTR) * 2 + a_lane;
    const uint32_t b_lane_b = (uint32_t)((((lane >> 4) & 1) * 8 + (lane & 7)) * QSTR +
                                         ((lane >> 3) & 1) * 8) * 2;

    for (int kt = 0; kt < nkv; kt++) {
        if (kt + 1 < nkv) {
            fl_load_kv(sb, (kt + 1) & 1, kt + 1, tid, K1g, K2g, Vg);
            CP_COMMIT();
            CP_WAIT(1);
        } else {
            CP_WAIT(0);
        }
        __syncthreads();
        const uint32_t st = sb + (uint32_t)(FL_ST0 + (kt & 1) * FL_STAGE) * 2;
        const bool msk = (kt >= nkv - 2);
        fl_stream(aQ1, st,                 st + 2 * FL_KV * 2, b_lane_b, kt, msk, row_g0, lane, O1, m1, l1);
        fl_stream(aQ2, st + FL_KV * 2,     st + 2 * FL_KV * 2, b_lane_b, kt, msk, row_g0, lane, O2, m2, l2);
        __syncthreads();
    }

    // epilogue: out = O1/l1 - lam*O2/l2, write split-bf16 [hi|hi|lo] into Ab
    float lamv = fminf(fmaxf(lam_p[h], 0.f), 1.f);
    float i10 = 1.f / l1[0], i11 = 1.f / l1[1];
    float i20 = lamv / l2[0], i21 = lamv / l2[1];
    const int row0 = q0 + wid * 16 + (lane >> 2);
    const int colb = h * 64 + 2 * (lane & 3);
    size_t rb0 = (size_t)(b * TT + row0) * KE;
    size_t rb1 = (size_t)(b * TT + row0 + 8) * KE;
#pragma unroll
    for (int nb = 0; nb < 8; nb++) {
        int col = colb + nb * 8;
        float x0 = O1[nb][0] * i10 - O2[nb][0] * i20;
        float x1 = O1[nb][1] * i10 - O2[nb][1] * i20;
        float y0 = O1[nb][2] * i11 - O2[nb][2] * i21;
        float y1 = O1[nb][3] * i11 - O2[nb][3] * i21;
        uint32_t hx = packbf(x0, x1);
        __nv_bfloat162 hv = *(__nv_bfloat162*)&hx;
        float2 hf = __bfloat1622float2(hv);
        uint32_t lx = packbf(x0 - hf.x, x1 - hf.y);
        *(uint32_t*)&Ab[rb0 + col] = hx;
        *(uint32_t*)&Ab[rb0 + 1024 + col] = hx;
        *(uint32_t*)&Ab[rb0 + 2048 + col] = lx;
        uint32_t hy = packbf(y0, y1);
        __nv_bfloat162 hv2 = *(__nv_bfloat162*)&hy;
        float2 hf2 = __bfloat1622float2(hv2);
        uint32_t ly = packbf(y0 - hf2.x, y1 - hf2.y);
        *(uint32_t*)&Ab[rb1 + col] = hy;
        *(uint32_t*)&Ab[rb1 + 1024 + col] = hy;
        *(uint32_t*)&Ab[rb1 + 2048 + col] = ly;
    }
}

// ---------------- launch ----------------
extern "C" void kernel_launch(void* const* d_in, const int* in_sizes, int n_in,
                              void* d_out, int out_size) {
    const float* x    = (const float*)d_in[0];
    const float* Wqkv = (const float*)d_in[2];
    const float* Wout = (const float*)d_in[3];
    const float* lam  = (const float*)d_in[4];
    float* out = (float*)d_out;

    float* qkv = nullptr;
    __nv_bfloat16 *Ab = nullptr, *Bq = nullptr, *Bo = nullptr;
    __nv_bfloat16 *Q1f = nullptr, *Q2f = nullptr, *K1f = nullptr, *K2f = nullptr, *Vt = nullptr;
    cudaGetSymbolAddress((void**)&qkv, g_qkv);
    cudaGetSymbolAddress((void**)&Ab,  g_Ab);
    cudaGetSymbolAddress((void**)&Bq,  g_Bq);
    cudaGetSymbolAddress((void**)&Bo,  g_Bo);
    cudaGetSymbolAddress((void**)&Q1f, g_Q1f);
    cudaGetSymbolAddress((void**)&Q2f, g_Q2f);
    cudaGetSymbolAddress((void**)&K1f, g_K1f);
    cudaGetSymbolAddress((void**)&K2f, g_K2f);
    cudaGetSymbolAddress((void**)&Vt,  g_Vt);

    cudaFuncSetAttribute(gemm_mma, cudaFuncAttributeMaxDynamicSharedMemorySize, GEMM_SMEM);
    cudaFuncSetAttribute(flash_mma, cudaFuncAttributeMaxDynamicSharedMemorySize, FL_SMEM_BYTES);

    // weight + input split conversions
    splitT<<<dim3(NQKV / 32, DM / 32), dim3(32, 8)>>>(Wqkv, Bq, NQKV);
    splitT<<<dim3(DM / 32, DM / 32), dim3(32, 8)>>>(Wout, Bo, DM);
    split_rows<<<(BT * DM + 255) / 256, 256>>>(x, Ab, BT * DM);

    // 1) QKV projection (HMMA)
    gemm_mma<<<dim3(NQKV / 128, BT / 128), 256, GEMM_SMEM>>>(Ab, Bq, qkv, NQKV);

    // 2) flash operand prep
    qkv_split<<<(BB * HH * TT * DD + 255) / 256, 256>>>(qkv, Q1f, Q2f, K1f, K2f);
    v_transpose<<<dim3(TT / 64, BB * HH), 256>>>(qkv, Vt);

    // 3) dual flash attention (HMMA); writes split-bf16 attn into Ab
    flash_mma<<<dim3(TT / 128, HH, BB), 256, FL_SMEM_BYTES>>>(Q1f, Q2f, K1f, K2f, Vt, lam, Ab);

    // 4) output projection (HMMA)
    gemm_mma<<<dim3(DM / 128, BT / 128), 256, GEMM_SMEM>>>(Ab, Bo, out, DM);
}

// round 8
// speedup vs baseline: 2.9868x; 1.1178x over previous
#include <cuda_runtime.h>
#include <cuda_bf16.h>
#include <math.h>
#include <cstdint>

// Problem constants
#define BB 2
#define TT 2048
#define DM 1024
#define HH 16
#define DD 64
#define NQKV 5120     // H * 5 * D
#define BT  4096      // B * T
#define KW  2048      // [hi(1024) | lo(1024)] operand layout

// ---------------- scratch (no cudaMalloc allowed) ----------------
__device__ __align__(16) float g_qkv[(size_t)BT * NQKV];               // 83.9 MB
__device__ __align__(16) __nv_bfloat16 g_Ab[(size_t)BT * KW];          // 16.8 MB
__device__ __align__(16) __nv_bfloat16 g_Bq[(size_t)NQKV * KW];        // 21.0 MB
__device__ __align__(16) __nv_bfloat16 g_Bo[(size_t)DM * KW];          // 4.2 MB
// flash operands: [bh][t][hi(64)|lo(64)] and V^T [bh][d][hi plane 2048 | lo plane 2048]
__device__ __align__(16) __nv_bfloat16 g_Q1f[(size_t)BB * HH * TT * 128];
__device__ __align__(16) __nv_bfloat16 g_Q2f[(size_t)BB * HH * TT * 128];
__device__ __align__(16) __nv_bfloat16 g_K1f[(size_t)BB * HH * TT * 128];
__device__ __align__(16) __nv_bfloat16 g_K2f[(size_t)BB * HH * TT * 128];
__device__ __align__(16) __nv_bfloat16 g_Vt [(size_t)BB * HH * DD * (2 * TT)];

// ================= helpers (plain sm_103-safe PTX only) =================
__device__ __forceinline__ uint32_t smem_u32(const void* p) {
    uint32_t a;
    asm("{ .reg .u64 t; cvta.to.shared.u64 t, %1; cvt.u32.u64 %0, t; }" : "=r"(a) : "l"(p));
    return a;
}
#define CP16(smem, gptr) \
    asm volatile("cp.async.cg.shared.global [%0], [%1], 16;" :: "r"(smem), "l"(gptr) : "memory")
#define CP_COMMIT() asm volatile("cp.async.commit_group;" ::: "memory")
#define CP_WAIT(n)  asm volatile("cp.async.wait_group %0;" :: "n"(n) : "memory")
#define LDSM_X4(r0, r1, r2, r3, addr) \
    asm volatile("ldmatrix.sync.aligned.m8n8.x4.shared.b16 {%0,%1,%2,%3}, [%4];" \
                 : "=r"(r0), "=r"(r1), "=r"(r2), "=r"(r3) : "r"(addr))
#define MMA16816(c, a, b) \
    asm volatile("mma.sync.aligned.m16n8k16.row.col.f32.bf16.bf16.f32 " \
                 "{%0,%1,%2,%3}, {%4,%5,%6,%7}, {%8,%9}, {%0,%1,%2,%3};" \
                 : "+f"((c)[0]), "+f"((c)[1]), "+f"((c)[2]), "+f"((c)[3]) \
                 : "r"((a)[0]), "r"((a)[1]), "r"((a)[2]), "r"((a)[3]), \
                   "r"((b)[0]), "r"((b)[1]))

__device__ __forceinline__ uint32_t packbf(float lo, float hi) {
    __nv_bfloat162 t = __floats2bfloat162_rn(lo, hi);
    return *(uint32_t*)&t;
}

// ================= conversion kernels =================
// fp32 [M,1024] row-major -> bf16 [M,2048]: cols [0,1024)=hi [1024,2048)=lo
__global__ void __launch_bounds__(256) split_rows(const float* __restrict__ in,
                                                  __nv_bfloat16* __restrict__ out, int total) {
    int idx = blockIdx.x * 256 + threadIdx.x;
    if (idx >= total) return;
    int m = idx >> 10, k = idx & 1023;
    float v = in[idx];
    __nv_bfloat16 h = __float2bfloat16(v);
    __nv_bfloat16 l = __float2bfloat16(v - __bfloat162float(h));
    size_t rb = (size_t)m * KW;
    out[rb + k] = h;
    out[rb + 1024 + k] = l;
}

// W fp32 [1024, N] -> bf16 [N, 2048] transposed: cols [0,1024)=hi [1024,2048)=lo
__global__ void __launch_bounds__(256) splitT(const float* __restrict__ W,
                                              __nv_bfloat16* __restrict__ out, int N) {
    __shared__ float smt[32][33];
    int n0 = blockIdx.x * 32, k0 = blockIdx.y * 32;
    int tx = threadIdx.x, ty = threadIdx.y;  // 32 x 8
#pragma unroll
    for (int i = 0; i < 4; i++)
        smt[ty * 4 + i][tx] = W[(size_t)(k0 + ty * 4 + i) * N + n0 + tx];
    __syncthreads();
#pragma unroll
    for (int i = 0; i < 4; i++) {
        int nn = ty * 4 + i;
        float v = smt[tx][nn];
        __nv_bfloat16 h = __float2bfloat16(v);
        __nv_bfloat16 l = __float2bfloat16(v - __bfloat162float(h));
        size_t rb = (size_t)(n0 + nn) * KW + k0 + tx;
        out[rb] = h;
        out[rb + 1024] = l;
    }
}

// g_qkv fp32 -> Q1/Q2/K1/K2 bf16 [bh][t][hi|lo]
__global__ void __launch_bounds__(256) qkv_split(const float* __restrict__ qkv,
                                                 __nv_bfloat16* __restrict__ Q1,
                                                 __nv_bfloat16* __restrict__ Q2,
                                                 __nv_bfloat16* __restrict__ K1,
                                                 __nv_bfloat16* __restrict__ K2) {
    int idx = blockIdx.x * 256 + threadIdx.x;           // over bh*T*64
    if (idx >= BB * HH * TT * DD) return;
    int d = idx & 63;
    int t = (idx >> 6) & (TT - 1);
    int bh = idx >> 17;
    int b = bh >> 4, h = bh & 15;
    const float* src = qkv + (size_t)(b * TT + t) * NQKV + h * 320 + d;
    size_t dst = ((size_t)bh * TT + t) * 128 + d;
    float v;
    __nv_bfloat16 hi;
    v = src[0];   hi = __float2bfloat16(v); Q1[dst] = hi; Q1[dst + 64] = __float2bfloat16(v - __bfloat162float(hi));
    v = src[64];  hi = __float2bfloat16(v); Q2[dst] = hi; Q2[dst + 64] = __float2bfloat16(v - __bfloat162float(hi));
    v = src[128]; hi = __float2bfloat16(v); K1[dst] = hi; K1[dst + 64] = __float2bfloat16(v - __bfloat162float(hi));
    v = src[192]; hi = __float2bfloat16(v); K2[dst] = hi; K2[dst + 64] = __float2bfloat16(v - __bfloat162float(hi));
}

// V fp32 [t, d] -> V^T bf16 [bh][d][hi plane t | lo plane t]
__global__ void __launch_bounds__(256) v_transpose(const float* __restrict__ qkv,
                                                   __nv_bfloat16* __restrict__ Vt) {
    __shared__ float tile[64][65];
    int t0 = blockIdx.x * 64;
    int bh = blockIdx.y;
    int b = bh >> 4, h = bh & 15;
    int c = threadIdx.x & 63, r4 = threadIdx.x >> 6;
#pragma unroll
    for (int rr = r4; rr < 64; rr += 4)
        tile[rr][c] = qkv[(size_t)(b * TT + t0 + rr) * NQKV + h * 320 + 256 + c];
    __syncthreads();
#pragma unroll
    for (int dd = r4; dd < 64; dd += 4) {
        float v = tile[c][dd];
        __nv_bfloat16 hi = __float2bfloat16(v);
        size_t base = ((size_t)bh * DD + dd) * (2 * TT) + t0 + c;
        Vt[base] = hi;
        Vt[base + TT] = __float2bfloat16(v - __bfloat162float(hi));
    }
}

// ========== HMMA split-bf16 GEMM: C[M,N] = (Ahi+Alo)[M,1024] @ (Bhi+Blo)[N,1024]^T ==========
// A,B stored [rows][hi(1024)|lo(1024)]. In-kernel combos: hi*hi + hi*lo + lo*hi.
// 128x128 CTA tile, 8 warps (4m x 2n), warp tile 32x64. 3-stage cp.async pipeline.
#define BKC 64
#define NKI (1024 / BKC)      // 16
#define ASTR 72               // smem row stride in bf16
#define TILE_E (128 * ASTR)   // one 128x64 tile (padded)
#define STAGE_E (4 * TILE_E)  // Ahi | Alo | Bhi | Blo
#define NSTAGE 3
#define GEMM_SMEM (NSTAGE * STAGE_E * 2)   // 221184 bytes

__global__ void __launch_bounds__(256) gemm_mma(const __nv_bfloat16* __restrict__ A,
                                                const __nv_bfloat16* __restrict__ B,
                                                float* __restrict__ C, int Ntot) {
    extern __shared__ __nv_bfloat16 smb[];
    const int tid = threadIdx.x;
    const int wid = tid >> 5;
    const int lane = tid & 31;
    const int m0 = blockIdx.y * 128;
    const int n0 = blockIdx.x * 128;
    const int wm = (wid >> 1) * 32;
    const int wn = (wid & 1) * 64;
    const uint32_t sbase = smem_u32(smb);

    // cp.async mapping: thread -> (row, 32-col half) of each 128x64 tile
    const int ldrow = tid >> 1;
    const int ldcol = (tid & 1) * 32;
    const __nv_bfloat16* Agp = A + (size_t)(m0 + ldrow) * KW + ldcol;
    const __nv_bfloat16* Bgp = B + (size_t)(n0 + ldrow) * KW + ldcol;
    const uint32_t st_off = (uint32_t)(ldrow * ASTR + ldcol) * 2;

    // ldmatrix offsets within one 128xASTR tile
    uint32_t aoff[2], boff[4];
#pragma unroll
    for (int mt = 0; mt < 2; mt++) {
        int row = wm + mt * 16 + (lane & 15);
        int col = (lane >> 4) * 8;
        aoff[mt] = (uint32_t)(row * ASTR + col) * 2;
    }
#pragma unroll
    for (int nt2 = 0; nt2 < 4; nt2++) {
        int n = wn + nt2 * 16 + ((lane >> 4) & 1) * 8 + (lane & 7);
        int k = ((lane >> 3) & 1) * 8;
        boff[nt2] = (uint32_t)(n * ASTR + k) * 2;
    }

    float acc[2][8][4];
#pragma unroll
    for (int mt = 0; mt < 2; mt++)
#pragma unroll
        for (int nt = 0; nt < 8; nt++)
#pragma unroll
            for (int j = 0; j < 4; j++) acc[mt][nt][j] = 0.f;

    // ---- stage loader: 4 tiles (Ahi, Alo, Bhi, Blo), 4 cp16 each per thread ----
#define LOAD_STAGE(s, k0)                                                          \
    do {                                                                           \
        uint32_t _b = sbase + (uint32_t)(s) * STAGE_E * 2 + st_off;                \
        const __nv_bfloat16* _a = Agp + (k0);                                      \
        const __nv_bfloat16* _bb = Bgp + (k0);                                     \
        _Pragma("unroll")                                                          \
        for (int j = 0; j < 4; j++) {                                              \
            CP16(_b + j * 16, _a + j * 8);                                         \
            CP16(_b + TILE_E * 2 + j * 16, _a + 1024 + j * 8);                     \
            CP16(_b + 2 * TILE_E * 2 + j * 16, _bb + j * 8);                       \
            CP16(_b + 3 * TILE_E * 2 + j * 16, _bb + 1024 + j * 8);                \
        }                                                                          \
    } while (0)

    LOAD_STAGE(0, 0);
    CP_COMMIT();
    LOAD_STAGE(1, BKC);
    CP_COMMIT();

    for (int i = 0; i < NKI; i++) {
        if (i + 1 < NKI) { CP_WAIT(1); } else { CP_WAIT(0); }
        __syncthreads();   // stage i visible to all; all warps done with stage i-1
        if (i + 2 < NKI) {
            LOAD_STAGE((i + 2) % NSTAGE, (i + 2) * BKC);
            CP_COMMIT();
        }
        const uint32_t stAh = sbase + (uint32_t)(i % NSTAGE) * STAGE_E * 2;
        const uint32_t stAl = stAh + TILE_E * 2;
        const uint32_t stBh = stAh + 2 * TILE_E * 2;
        const uint32_t stBl = stAh + 3 * TILE_E * 2;
#pragma unroll
        for (int ks = 0; ks < 4; ks++) {
            uint32_t ah[2][4], al[2][4], bh[4][4], bl[4][4];
#pragma unroll
            for (int mt = 0; mt < 2; mt++) {
                LDSM_X4(ah[mt][0], ah[mt][1], ah[mt][2], ah[mt][3], stAh + aoff[mt] + ks * 32);
                LDSM_X4(al[mt][0], al[mt][1], al[mt][2], al[mt][3], stAl + aoff[mt] + ks * 32);
            }
#pragma unroll
            for (int nt2 = 0; nt2 < 4; nt2++) {
                LDSM_X4(bh[nt2][0], bh[nt2][1], bh[nt2][2], bh[nt2][3], stBh + boff[nt2] + ks * 32);
                LDSM_X4(bl[nt2][0], bl[nt2][1], bl[nt2][2], bl[nt2][3], stBl + boff[nt2] + ks * 32);
            }
#pragma unroll
            for (int mt = 0; mt < 2; mt++)
#pragma unroll
                for (int nt2 = 0; nt2 < 4; nt2++) {
                    MMA16816(acc[mt][2 * nt2],     ah[mt], (&bh[nt2][0]));
                    MMA16816(acc[mt][2 * nt2 + 1], ah[mt], (&bh[nt2][2]));
                    MMA16816(acc[mt][2 * nt2],     ah[mt], (&bl[nt2][0]));
                    MMA16816(acc[mt][2 * nt2 + 1], ah[mt], (&bl[nt2][2]));
                    MMA16816(acc[mt][2 * nt2],     al[mt], (&bh[nt2][0]));
                    MMA16816(acc[mt][2 * nt2 + 1], al[mt], (&bh[nt2][2]));
                }
        }
    }
#undef LOAD_STAGE

    // epilogue: write fp32 C
#pragma unroll
    for (int mt = 0; mt < 2; mt++) {
        int r0 = m0 + wm + mt * 16 + (lane >> 2);
        int c0 = n0 + wn + (lane & 3) * 2;
        float* p0 = C + (size_t)r0 * Ntot + c0;
        float* p1 = C + (size_t)(r0 + 8) * Ntot + c0;
#pragma unroll
        for (int nt = 0; nt < 8; nt++) {
            *(float2*)(p0 + nt * 8) = make_float2(acc[mt][nt][0], acc[mt][nt][1]);
            *(float2*)(p1 + nt * 8) = make_float2(acc[mt][nt][2], acc[mt][nt][3]);
        }
    }
}

// ================= HMMA dual flash attention =================
// CTA: 128 q-rows of one (b,h); 8 warps, warp = m16. kv tiles of 64, double-buffered.
#define QSTR 136                      // bf16 row stride (272B, conflict-free)
#define FL_Q1 0
#define FL_Q2 (128 * QSTR)
#define FL_ST0 (2 * 128 * QSTR)
#define FL_KV (64 * QSTR)             // one tensor in a stage
#define FL_STAGE (3 * FL_KV)          // K1 | K2 | Vt
#define FL_SMEM_BYTES ((2 * 128 * QSTR + 2 * FL_STAGE) * 2)   // 174080

__device__ __forceinline__ void fl_load_kv(uint32_t sb, int st, int kt, int tid,
                                           const __nv_bfloat16* K1g,
                                           const __nv_bfloat16* K2g,
                                           const __nv_bfloat16* Vg) {
    int r = tid >> 2, qd = tid & 3;
    uint32_t base = sb + (uint32_t)(FL_ST0 + st * FL_STAGE) * 2;
    uint32_t o = (uint32_t)(r * QSTR + qd * 32) * 2;
    const __nv_bfloat16* k1 = K1g + (size_t)(kt * 64 + r) * 128 + qd * 32;
    const __nv_bfloat16* k2 = K2g + (size_t)(kt * 64 + r) * 128 + qd * 32;
    const __nv_bfloat16* vv = Vg + (size_t)r * (2 * TT) + ((qd >> 1) ? TT : 0) + kt * 64 + (qd & 1) * 32;
#pragma unroll
    for (int j = 0; j < 4; j++) {
        CP16(base + o + j * 16, k1 + j * 8);
        CP16(base + FL_KV * 2 + o + j * 16, k2 + j * 8);
        CP16(base + 2 * FL_KV * 2 + o + j * 16, vv + j * 8);
    }
}

// one stream (S = Q K^T split, online softmax, O += P V split)
__device__ __forceinline__ void fl_stream(uint32_t a_addr, uint32_t kstage, uint32_t vstage,
                                          uint32_t b_lane_b, int kt, bool need_mask,
                                          int row_g0, int lane,
                                          float O[8][4], float* mst, float* lst) {
    float acc[8][4];
#pragma unroll
    for (int nb = 0; nb < 8; nb++)
#pragma unroll
        for (int j = 0; j < 4; j++) acc[nb][j] = 0.f;

    // S = Q K^T with 3-combo split: (hi,hi) (hi,lo) (lo,hi); k16 steps
    const int qoffs[12] = {0,16,32,48, 0,16,32,48, 64,80,96,112};
    const int koffs[12] = {0,16,32,48, 64,80,96,112, 0,16,32,48};
#pragma unroll
    for (int s = 0; s < 12; s++) {
        uint32_t af[4];
        LDSM_X4(af[0], af[1], af[2], af[3], a_addr + qoffs[s] * 2);
#pragma unroll
        for (int nt2 = 0; nt2 < 4; nt2++) {
            uint32_t bf[4];
            LDSM_X4(bf[0], bf[1], bf[2], bf[3],
                    kstage + b_lane_b + (uint32_t)(nt2 * 16 * QSTR + koffs[s]) * 2);
            MMA16816(acc[2 * nt2],     af, (&bf[0]));
            MMA16816(acc[2 * nt2 + 1], af, (&bf[2]));
        }
    }

    // scale + causal mask
#pragma unroll
    for (int nb = 0; nb < 8; nb++)
#pragma unroll
        for (int j = 0; j < 4; j++) {
            float v = acc[nb][j] * 0.125f;
            if (need_mask) {
                int col = kt * 64 + nb * 8 + 2 * (lane & 3) + (j & 1);
                int row = row_g0 + ((j >> 1) << 3);
                if (col > row) v = -1e30f;
            }
            acc[nb][j] = v;
        }

    // online softmax (rows r and r+8)
    float mx0 = -1e30f, mx1 = -1e30f;
#pragma unroll
    for (int nb = 0; nb < 8; nb++) {
        mx0 = fmaxf(mx0, fmaxf(acc[nb][0], acc[nb][1]));
        mx1 = fmaxf(mx1, fmaxf(acc[nb][2], acc[nb][3]));
    }
    mx0 = fmaxf(mx0, __shfl_xor_sync(0xffffffffu, mx0, 1));
    mx0 = fmaxf(mx0, __shfl_xor_sync(0xffffffffu, mx0, 2));
    mx1 = fmaxf(mx1, __shfl_xor_sync(0xffffffffu, mx1, 1));
    mx1 = fmaxf(mx1, __shfl_xor_sync(0xffffffffu, mx1, 2));
    float mn0 = fmaxf(mst[0], mx0), mn1 = fmaxf(mst[1], mx1);
    float al0 = __expf(mst[0] - mn0), al1 = __expf(mst[1] - mn1);
    float s0 = 0.f, s1 = 0.f;
#pragma unroll
    for (int nb = 0; nb < 8; nb++) {
        acc[nb][0] = __expf(acc[nb][0] - mn0);
        acc[nb][1] = __expf(acc[nb][1] - mn0);
        acc[nb][2] = __expf(acc[nb][2] - mn1);
        acc[nb][3] = __expf(acc[nb][3] - mn1);
        s0 += acc[nb][0] + acc[nb][1];
        s1 += acc[nb][2] + acc[nb][3];
    }
    s0 += __shfl_xor_sync(0xffffffffu, s0, 1);
    s0 += __shfl_xor_sync(0xffffffffu, s0, 2);
    s1 += __shfl_xor_sync(0xffffffffu, s1, 1);
    s1 += __shfl_xor_sync(0xffffffffu, s1, 2);
    lst[0] = lst[0] * al0 + s0;
    lst[1] = lst[1] * al1 + s1;
    mst[0] = mn0;
    mst[1] = mn1;
#pragma unroll
    for (int nb = 0; nb < 8; nb++) {
        O[nb][0] *= al0; O[nb][1] *= al0;
        O[nb][2] *= al1; O[nb][3] *= al1;
    }

    // O += P V (register-direct P fragments, split: Ph*Vhi + Pl*Vhi + Ph*Vlo)
#pragma unroll
    for (int s = 0; s < 4; s++) {
        uint32_t ah[4], al_[4];
        ah[0] = packbf(acc[2 * s][0],     acc[2 * s][1]);
        ah[1] = packbf(acc[2 * s][2],     acc[2 * s][3]);
        ah[2] = packbf(acc[2 * s + 1][0], acc[2 * s + 1][1]);
        ah[3] = packbf(acc[2 * s + 1][2], acc[2 * s + 1][3]);
#pragma unroll
        for (int q = 0; q < 4; q++) {
            __nv_bfloat162 hv = *(__nv_bfloat162*)&ah[q];
            float2 hf = __bfloat1622float2(hv);
            int nb = 2 * s + (q >> 1);
            int j0 = (q & 1) * 2;
            al_[q] = packbf(acc[nb][j0] - hf.x, acc[nb][j0 + 1] - hf.y);
        }
#pragma unroll
        for (int nt2 = 0; nt2 < 4; nt2++) {
            uint32_t bh_[4], bl_[4];
            uint32_t vb = vstage + b_lane_b + (uint32_t)(nt2 * 16 * QSTR) * 2;
            LDSM_X4(bh_[0], bh_[1], bh_[2], bh_[3], vb + (uint32_t)(s * 16) * 2);
            LDSM_X4(bl_[0], bl_[1], bl_[2], bl_[3], vb + (uint32_t)(64 + s * 16) * 2);
            MMA16816(O[2 * nt2],     ah,  (&bh_[0]));
            MMA16816(O[2 * nt2 + 1], ah,  (&bh_[2]));
            MMA16816(O[2 * nt2],     al_, (&bh_[0]));
            MMA16816(O[2 * nt2 + 1], al_, (&bh_[2]));
            MMA16816(O[2 * nt2],     ah,  (&bl_[0]));
            MMA16816(O[2 * nt2 + 1], ah,  (&bl_[2]));
        }
    }
}

__global__ void __launch_bounds__(256) flash_mma(
    const __nv_bfloat16* __restrict__ Q1f, const __nv_bfloat16* __restrict__ Q2f,
    const __nv_bfloat16* __restrict__ K1f, const __nv_bfloat16* __restrict__ K2f,
    const __nv_bfloat16* __restrict__ Vtg, const float* __restrict__ lam_p,
    __nv_bfloat16* __restrict__ Ab) {
    extern __shared__ __nv_bfloat16 sfb[];
    const uint32_t sb = smem_u32(sfb);
    const int tid = threadIdx.x, wid = tid >> 5, lane = tid & 31;
    const int qrev = gridDim.x - 1 - blockIdx.x;    // heavy CTAs first
    const int q0 = qrev * 128;
    const int h = blockIdx.y, b = blockIdx.z;
    const int bh = b * HH + h;
    const int nkv = 2 * qrev + 2;

    const __nv_bfloat16* Q1g = Q1f + ((size_t)bh * TT + q0) * 128;
    const __nv_bfloat16* Q2g = Q2f + ((size_t)bh * TT + q0) * 128;
    const __nv_bfloat16* K1g = K1f + (size_t)bh * TT * 128;
    const __nv_bfloat16* K2g = K2f + (size_t)bh * TT * 128;
    const __nv_bfloat16* Vg  = Vtg + (size_t)bh * DD * (2 * TT);

    // Q tiles via cp.async
    {
        int row = tid >> 1, hf = (tid & 1) * 64;
        uint32_t d1 = sb + (uint32_t)(FL_Q1 + row * QSTR + hf) * 2;
        uint32_t d2 = sb + (uint32_t)(FL_Q2 + row * QSTR + hf) * 2;
        const __nv_bfloat16* s1 = Q1g + row * 128 + hf;
        const __nv_bfloat16* s2 = Q2g + row * 128 + hf;
#pragma unroll
        for (int j = 0; j < 8; j++) { CP16(d1 + j * 16, s1 + j * 8); CP16(d2 + j * 16, s2 + j * 8); }
    }
    fl_load_kv(sb, 0, 0, tid, K1g, K2g, Vg);
    CP_COMMIT();

    float O1[8][4], O2[8][4];
#pragma unroll
    for (int nb = 0; nb < 8; nb++)
#pragma unroll
        for (int j = 0; j < 4; j++) { O1[nb][j] = 0.f; O2[nb][j] = 0.f; }
    float m1[2] = {-1e30f, -1e30f}, l1[2] = {0.f, 0.f};
    float m2[2] = {-1e30f, -1e30f}, l2[2] = {0.f, 0.f};

    const int row_g0 = q0 + wid * 16 + (lane >> 2);
    const uint32_t a_lane = (uint32_t)((lane & 15) * QSTR + (lane >> 4) * 8) * 2;
    const uint32_t aQ1 = sb + (uint32_t)(FL_Q1 + wid * 16 * QSTR) * 2 + a_lane;
    const uint32_t aQ2 = sb + (uint32_t)(FL_Q2 + wid * 16 * QSTR) * 2 + a_lane;
    const uint32_t b_lane_b = (uint32_t)((((lane >> 4) & 1) * 8 + (lane & 7)) * QSTR +
                                         ((lane >> 3) & 1) * 8) * 2;

    for (int kt = 0; kt < nkv; kt++) {
        if (kt + 1 < nkv) {
            fl_load_kv(sb, (kt + 1) & 1, kt + 1, tid, K1g, K2g, Vg);
            CP_COMMIT();
            CP_WAIT(1);
        } else {
            CP_WAIT(0);
        }
        __syncthreads();
        const uint32_t st = sb + (uint32_t)(FL_ST0 + (kt & 1) * FL_STAGE) * 2;
        const bool msk = (kt >= nkv - 2);
        fl_stream(aQ1, st,                 st + 2 * FL_KV * 2, b_lane_b, kt, msk, row_g0, lane, O1, m1, l1);
        fl_stream(aQ2, st + FL_KV * 2,     st + 2 * FL_KV * 2, b_lane_b, kt, msk, row_g0, lane, O2, m2, l2);
        __syncthreads();
    }

    // epilogue: out = O1/l1 - lam*O2/l2, write split-bf16 [hi|lo] into Ab
    float lamv = fminf(fmaxf(lam_p[h], 0.f), 1.f);
    float i10 = 1.f / l1[0], i11 = 1.f / l1[1];
    float i20 = lamv / l2[0], i21 = lamv / l2[1];
    const int row0 = q0 + wid * 16 + (lane >> 2);
    const int colb = h * 64 + 2 * (lane & 3);
    size_t rb0 = (size_t)(b * TT + row0) * KW;
    size_t rb1 = (size_t)(b * TT + row0 + 8) * KW;
#pragma unroll
    for (int nb = 0; nb < 8; nb++) {
        int col = colb + nb * 8;
        float x0 = O1[nb][0] * i10 - O2[nb][0] * i20;
        float x1 = O1[nb][1] * i10 - O2[nb][1] * i20;
        float y0 = O1[nb][2] * i11 - O2[nb][2] * i21;
        float y1 = O1[nb][3] * i11 - O2[nb][3] * i21;
        uint32_t hx = packbf(x0, x1);
        __nv_bfloat162 hv = *(__nv_bfloat162*)&hx;
        float2 hf = __bfloat1622float2(hv);
        uint32_t lx = packbf(x0 - hf.x, x1 - hf.y);
        *(uint32_t*)&Ab[rb0 + col] = hx;
        *(uint32_t*)&Ab[rb0 + 1024 + col] = lx;
        uint32_t hy = packbf(y0, y1);
        __nv_bfloat162 hv2 = *(__nv_bfloat162*)&hy;
        float2 hf2 = __bfloat1622float2(hv2);
        uint32_t ly = packbf(y0 - hf2.x, y1 - hf2.y);
        *(uint32_t*)&Ab[rb1 + col] = hy;
        *(uint32_t*)&Ab[rb1 + 1024 + col] = ly;
    }
}

// ---------------- launch ----------------
extern "C" void kernel_launch(void* const* d_in, const int* in_sizes, int n_in,
                              void* d_out, int out_size) {
    const float* x    = (const float*)d_in[0];
    const float* Wqkv = (const float*)d_in[2];
    const float* Wout = (const float*)d_in[3];
    const float* lam  = (const float*)d_in[4];
    float* out = (float*)d_out;

    float* qkv = nullptr;
    __nv_bfloat16 *Ab = nullptr, *Bq = nullptr, *Bo = nullptr;
    __nv_bfloat16 *Q1f = nullptr, *Q2f = nullptr, *K1f = nullptr, *K2f = nullptr, *Vt = nullptr;
    cudaGetSymbolAddress((void**)&qkv, g_qkv);
    cudaGetSymbolAddress((void**)&Ab,  g_Ab);
    cudaGetSymbolAddress((void**)&Bq,  g_Bq);
    cudaGetSymbolAddress((void**)&Bo,  g_Bo);
    cudaGetSymbolAddress((void**)&Q1f, g_Q1f);
    cudaGetSymbolAddress((void**)&Q2f, g_Q2f);
    cudaGetSymbolAddress((void**)&K1f, g_K1f);
    cudaGetSymbolAddress((void**)&K2f, g_K2f);
    cudaGetSymbolAddress((void**)&Vt,  g_Vt);

    cudaFuncSetAttribute(gemm_mma, cudaFuncAttributeMaxDynamicSharedMemorySize, GEMM_SMEM);
    cudaFuncSetAttribute(flash_mma, cudaFuncAttributeMaxDynamicSharedMemorySize, FL_SMEM_BYTES);

    // weight + input split conversions
    splitT<<<dim3(NQKV / 32, DM / 32), dim3(32, 8)>>>(Wqkv, Bq, NQKV);
    splitT<<<dim3(DM / 32, DM / 32), dim3(32, 8)>>>(Wout, Bo, DM);
    split_rows<<<(BT * DM + 255) / 256, 256>>>(x, Ab, BT * DM);

    // 1) QKV projection (HMMA, in-kernel split combos)
    gemm_mma<<<dim3(NQKV / 128, BT / 128), 256, GEMM_SMEM>>>(Ab, Bq, qkv, NQKV);

    // 2) flash operand prep
    qkv_split<<<(BB * HH * TT * DD + 255) / 256, 256>>>(qkv, Q1f, Q2f, K1f, K2f);
    v_transpose<<<dim3(TT / 64, BB * HH), 256>>>(qkv, Vt);

    // 3) dual flash attention (HMMA); writes split-bf16 attn into Ab
    flash_mma<<<dim3(TT / 128, HH, BB), 256, FL_SMEM_BYTES>>>(Q1f, Q2f, K1f, K2f, Vt, lam, Ab);

    // 4) output projection (HMMA)
    gemm_mma<<<dim3(DM / 128, BT / 128), 256, GEMM_SMEM>>>(Ab, Bo, out, DM);
}

// round 9
// speedup vs baseline: 3.8806x; 1.2992x over previous
#include <cuda_runtime.h>
#include <cuda_bf16.h>
#include <cuda_fp16.h>
#include <math.h>
#include <cstdint>

// Problem constants
#define BB 2
#define TT 2048
#define DM 1024
#define HH 16
#define DD 64
#define NQKV 5120     // H * 5 * D
#define BT  4096      // B * T
#define KW  2048      // [hi(1024) | lo(1024)] operand layout for GEMMs

// ---------------- scratch (no cudaMalloc allowed) ----------------
__device__ __align__(16) float g_qkv[(size_t)BT * NQKV];               // 83.9 MB
__device__ __align__(16) __nv_bfloat16 g_Ab[(size_t)BT * KW];          // 16.8 MB
__device__ __align__(16) __nv_bfloat16 g_Bq[(size_t)NQKV * KW];        // 21.0 MB
__device__ __align__(16) __nv_bfloat16 g_Bo[(size_t)DM * KW];          // 4.2 MB
// flash operands (fp16 single-plane): [bh][t][64], V^T [bh][d][t]
__device__ __align__(16) __half g_Q1f[(size_t)BB * HH * TT * DD];
__device__ __align__(16) __half g_Q2f[(size_t)BB * HH * TT * DD];
__device__ __align__(16) __half g_K1f[(size_t)BB * HH * TT * DD];
__device__ __align__(16) __half g_K2f[(size_t)BB * HH * TT * DD];
__device__ __align__(16) __half g_Vt [(size_t)BB * HH * DD * TT];

// ================= helpers (plain sm_103-safe PTX only) =================
__device__ __forceinline__ uint32_t smem_u32(const void* p) {
    uint32_t a;
    asm("{ .reg .u64 t; cvta.to.shared.u64 t, %1; cvt.u32.u64 %0, t; }" : "=r"(a) : "l"(p));
    return a;
}
#define CP16(smem, gptr) \
    asm volatile("cp.async.cg.shared.global [%0], [%1], 16;" :: "r"(smem), "l"(gptr) : "memory")
#define CP_COMMIT() asm volatile("cp.async.commit_group;" ::: "memory")
#define CP_WAIT(n)  asm volatile("cp.async.wait_group %0;" :: "n"(n) : "memory")
#define LDSM_X4(r0, r1, r2, r3, addr) \
    asm volatile("ldmatrix.sync.aligned.m8n8.x4.shared.b16 {%0,%1,%2,%3}, [%4];" \
                 : "=r"(r0), "=r"(r1), "=r"(r2), "=r"(r3) : "r"(addr))
#define MMA16816(c, a, b) \
    asm volatile("mma.sync.aligned.m16n8k16.row.col.f32.bf16.bf16.f32 " \
                 "{%0,%1,%2,%3}, {%4,%5,%6,%7}, {%8,%9}, {%0,%1,%2,%3};" \
                 : "+f"((c)[0]), "+f"((c)[1]), "+f"((c)[2]), "+f"((c)[3]) \
                 : "r"((a)[0]), "r"((a)[1]), "r"((a)[2]), "r"((a)[3]), \
                   "r"((b)[0]), "r"((b)[1]))
#define MMAH16816(c, a, b) \
    asm volatile("mma.sync.aligned.m16n8k16.row.col.f32.f16.f16.f32 " \
                 "{%0,%1,%2,%3}, {%4,%5,%6,%7}, {%8,%9}, {%0,%1,%2,%3};" \
                 : "+f"((c)[0]), "+f"((c)[1]), "+f"((c)[2]), "+f"((c)[3]) \
                 : "r"((a)[0]), "r"((a)[1]), "r"((a)[2]), "r"((a)[3]), \
                   "r"((b)[0]), "r"((b)[1]))

__device__ __forceinline__ uint32_t packbf(float lo, float hi) {
    __nv_bfloat162 t = __floats2bfloat162_rn(lo, hi);
    return *(uint32_t*)&t;
}
__device__ __forceinline__ uint32_t packh(float lo, float hi) {
    __half2 t = __floats2half2_rn(lo, hi);
    return *(uint32_t*)&t;
}

// ================= conversion kernels =================
// fp32 [M,1024] row-major -> bf16 [M,2048]: cols [0,1024)=hi [1024,2048)=lo
__global__ void __launch_bounds__(256) split_rows(const float* __restrict__ in,
                                                  __nv_bfloat16* __restrict__ out, int total) {
    int idx = blockIdx.x * 256 + threadIdx.x;
    if (idx >= total) return;
    int m = idx >> 10, k = idx & 1023;
    float v = in[idx];
    __nv_bfloat16 h = __float2bfloat16(v);
    __nv_bfloat16 l = __float2bfloat16(v - __bfloat162float(h));
    size_t rb = (size_t)m * KW;
    out[rb + k] = h;
    out[rb + 1024 + k] = l;
}

// W fp32 [1024, N] -> bf16 [N, 2048] transposed: cols [0,1024)=hi [1024,2048)=lo
__global__ void __launch_bounds__(256) splitT(const float* __restrict__ W,
                                              __nv_bfloat16* __restrict__ out, int N) {
    __shared__ float smt[32][33];
    int n0 = blockIdx.x * 32, k0 = blockIdx.y * 32;
    int tx = threadIdx.x, ty = threadIdx.y;  // 32 x 8
#pragma unroll
    for (int i = 0; i < 4; i++)
        smt[ty * 4 + i][tx] = W[(size_t)(k0 + ty * 4 + i) * N + n0 + tx];
    __syncthreads();
#pragma unroll
    for (int i = 0; i < 4; i++) {
        int nn = ty * 4 + i;
        float v = smt[tx][nn];
        __nv_bfloat16 h = __float2bfloat16(v);
        __nv_bfloat16 l = __float2bfloat16(v - __bfloat162float(h));
        size_t rb = (size_t)(n0 + nn) * KW + k0 + tx;
        out[rb] = h;
        out[rb + 1024] = l;
    }
}

// g_qkv fp32 -> Q1/Q2/K1/K2 fp16 [bh][t][64]
__global__ void __launch_bounds__(256) qkv_split(const float* __restrict__ qkv,
                                                 __half* __restrict__ Q1,
                                                 __half* __restrict__ Q2,
                                                 __half* __restrict__ K1,
                                                 __half* __restrict__ K2) {
    int idx = blockIdx.x * 256 + threadIdx.x;           // over bh*T*64
    if (idx >= BB * HH * TT * DD) return;
    int d = idx & 63;
    int t = (idx >> 6) & (TT - 1);
    int bh = idx >> 17;
    int b = bh >> 4, h = bh & 15;
    const float* src = qkv + (size_t)(b * TT + t) * NQKV + h * 320 + d;
    size_t dst = ((size_t)bh * TT + t) * DD + d;
    Q1[dst] = __float2half(src[0]);
    Q2[dst] = __float2half(src[64]);
    K1[dst] = __float2half(src[128]);
    K2[dst] = __float2half(src[192]);
}

// V fp32 [t, d] -> V^T fp16 [bh][d][t]
__global__ void __launch_bounds__(256) v_transpose(const float* __restrict__ qkv,
                                                   __half* __restrict__ Vt) {
    __shared__ float tile[64][65];
    int t0 = blockIdx.x * 64;
    int bh = blockIdx.y;
    int b = bh >> 4, h = bh & 15;
    int c = threadIdx.x & 63, r4 = threadIdx.x >> 6;
#pragma unroll
    for (int rr = r4; rr < 64; rr += 4)
        tile[rr][c] = qkv[(size_t)(b * TT + t0 + rr) * NQKV + h * 320 + 256 + c];
    __syncthreads();
#pragma unroll
    for (int dd = r4; dd < 64; dd += 4)
        Vt[((size_t)bh * DD + dd) * TT + t0 + c] = __float2half(tile[c][dd]);
}

// ========== HMMA split-bf16 GEMM: C[M,N] = (Ahi+Alo)[M,1024] @ (Bhi+Blo)[N,1024]^T ==========
#define BKC 64
#define NKI (1024 / BKC)      // 16
#define ASTR 72               // smem row stride in bf16
#define TILE_E (128 * ASTR)   // one 128x64 tile (padded)
#define STAGE_E (4 * TILE_E)  // Ahi | Alo | Bhi | Blo
#define NSTAGE 3
#define GEMM_SMEM (NSTAGE * STAGE_E * 2)   // 221184 bytes

__global__ void __launch_bounds__(256) gemm_mma(const __nv_bfloat16* __restrict__ A,
                                                const __nv_bfloat16* __restrict__ B,
                                                float* __restrict__ C, int Ntot) {
    extern __shared__ __nv_bfloat16 smb[];
    const int tid = threadIdx.x;
    const int wid = tid >> 5;
    const int lane = tid & 31;
    const int m0 = blockIdx.y * 128;
    const int n0 = blockIdx.x * 128;
    const int wm = (wid >> 1) * 32;
    const int wn = (wid & 1) * 64;
    const uint32_t sbase = smem_u32(smb);

    const int ldrow = tid >> 1;
    const int ldcol = (tid & 1) * 32;
    const __nv_bfloat16* Agp = A + (size_t)(m0 + ldrow) * KW + ldcol;
    const __nv_bfloat16* Bgp = B + (size_t)(n0 + ldrow) * KW + ldcol;
    const uint32_t st_off = (uint32_t)(ldrow * ASTR + ldcol) * 2;

    uint32_t aoff[2], boff[4];
#pragma unroll
    for (int mt = 0; mt < 2; mt++) {
        int row = wm + mt * 16 + (lane & 15);
        int col = (lane >> 4) * 8;
        aoff[mt] = (uint32_t)(row * ASTR + col) * 2;
    }
#pragma unroll
    for (int nt2 = 0; nt2 < 4; nt2++) {
        int n = wn + nt2 * 16 + ((lane >> 4) & 1) * 8 + (lane & 7);
        int k = ((lane >> 3) & 1) * 8;
        boff[nt2] = (uint32_t)(n * ASTR + k) * 2;
    }

    float acc[2][8][4];
#pragma unroll
    for (int mt = 0; mt < 2; mt++)
#pragma unroll
        for (int nt = 0; nt < 8; nt++)
#pragma unroll
            for (int j = 0; j < 4; j++) acc[mt][nt][j] = 0.f;

#define LOAD_STAGE(s, k0)                                                          \
    do {                                                                           \
        uint32_t _b = sbase + (uint32_t)(s) * STAGE_E * 2 + st_off;                \
        const __nv_bfloat16* _a = Agp + (k0);                                      \
        const __nv_bfloat16* _bb = Bgp + (k0);                                     \
        _Pragma("unroll")                                                          \
        for (int j = 0; j < 4; j++) {                                              \
            CP16(_b + j * 16, _a + j * 8);                                         \
            CP16(_b + TILE_E * 2 + j * 16, _a + 1024 + j * 8);                     \
            CP16(_b + 2 * TILE_E * 2 + j * 16, _bb + j * 8);                       \
            CP16(_b + 3 * TILE_E * 2 + j * 16, _bb + 1024 + j * 8);                \
        }                                                                          \
    } while (0)

    LOAD_STAGE(0, 0);
    CP_COMMIT();
    LOAD_STAGE(1, BKC);
    CP_COMMIT();

    for (int i = 0; i < NKI; i++) {
        if (i + 1 < NKI) { CP_WAIT(1); } else { CP_WAIT(0); }
        __syncthreads();
        if (i + 2 < NKI) {
            LOAD_STAGE((i + 2) % NSTAGE, (i + 2) * BKC);
            CP_COMMIT();
        }
        const uint32_t stAh = sbase + (uint32_t)(i % NSTAGE) * STAGE_E * 2;
        const uint32_t stAl = stAh + TILE_E * 2;
        const uint32_t stBh = stAh + 2 * TILE_E * 2;
        const uint32_t stBl = stAh + 3 * TILE_E * 2;
#pragma unroll
        for (int ks = 0; ks < 4; ks++) {
            uint32_t ah[2][4], al[2][4], bh[4][4], bl[4][4];
#pragma unroll
            for (int mt = 0; mt < 2; mt++) {
                LDSM_X4(ah[mt][0], ah[mt][1], ah[mt][2], ah[mt][3], stAh + aoff[mt] + ks * 32);
                LDSM_X4(al[mt][0], al[mt][1], al[mt][2], al[mt][3], stAl + aoff[mt] + ks * 32);
            }
#pragma unroll
            for (int nt2 = 0; nt2 < 4; nt2++) {
                LDSM_X4(bh[nt2][0], bh[nt2][1], bh[nt2][2], bh[nt2][3], stBh + boff[nt2] + ks * 32);
                LDSM_X4(bl[nt2][0], bl[nt2][1], bl[nt2][2], bl[nt2][3], stBl + boff[nt2] + ks * 32);
            }
#pragma unroll
            for (int mt = 0; mt < 2; mt++)
#pragma unroll
                for (int nt2 = 0; nt2 < 4; nt2++) {
                    MMA16816(acc[mt][2 * nt2],     ah[mt], (&bh[nt2][0]));
                    MMA16816(acc[mt][2 * nt2 + 1], ah[mt], (&bh[nt2][2]));
                    MMA16816(acc[mt][2 * nt2],     ah[mt], (&bl[nt2][0]));
                    MMA16816(acc[mt][2 * nt2 + 1], ah[mt], (&bl[nt2][2]));
                    MMA16816(acc[mt][2 * nt2],     al[mt], (&bh[nt2][0]));
                    MMA16816(acc[mt][2 * nt2 + 1], al[mt], (&bh[nt2][2]));
                }
        }
    }
#undef LOAD_STAGE

#pragma unroll
    for (int mt = 0; mt < 2; mt++) {
        int r0 = m0 + wm + mt * 16 + (lane >> 2);
        int c0 = n0 + wn + (lane & 3) * 2;
        float* p0 = C + (size_t)r0 * Ntot + c0;
        float* p1 = C + (size_t)(r0 + 8) * Ntot + c0;
#pragma unroll
        for (int nt = 0; nt < 8; nt++) {
            *(float2*)(p0 + nt * 8) = make_float2(acc[mt][nt][0], acc[mt][nt][1]);
            *(float2*)(p1 + nt * 8) = make_float2(acc[mt][nt][2], acc[mt][nt][3]);
        }
    }
}

// ================= fp16 HMMA dual flash attention =================
// CTA: 128 q-rows of one (b,h); 8 warps, warp = m16. kv tiles of 64, double-buffered.
#define QS2 72                        // fp16 row stride (144B)
#define FL_Q1 0
#define FL_Q2 (128 * QS2)
#define FL_ST0 (2 * 128 * QS2)
#define FL_KV (64 * QS2)              // one tensor in a stage
#define FL_STAGE (3 * FL_KV)          // K1 | K2 | Vt
#define FL_SMEM_BYTES ((2 * 128 * QS2 + 2 * FL_STAGE) * 2)   // 92160

__device__ __forceinline__ void fl_load_kv(uint32_t sb, int st, int kt, int tid,
                                           const __half* K1g,
                                           const __half* K2g,
                                           const __half* Vg) {
    int r = tid >> 2, qd = tid & 3;   // row 0..63, 16-elem quarter
    uint32_t base = sb + (uint32_t)(FL_ST0 + st * FL_STAGE) * 2;
    uint32_t o = (uint32_t)(r * QS2 + qd * 16) * 2;
    const __half* k1 = K1g + (size_t)(kt * 64 + r) * DD + qd * 16;
    const __half* k2 = K2g + (size_t)(kt * 64 + r) * DD + qd * 16;
    const __half* vv = Vg + (size_t)r * TT + kt * 64 + qd * 16;
#pragma unroll
    for (int j = 0; j < 2; j++) {
        CP16(base + o + j * 16, k1 + j * 8);
        CP16(base + FL_KV * 2 + o + j * 16, k2 + j * 8);
        CP16(base + 2 * FL_KV * 2 + o + j * 16, vv + j * 8);
    }
}

// one stream: S = Q K^T (fp16), online softmax, O += P V (fp16)
__device__ __forceinline__ void fl_stream(uint32_t a_addr, uint32_t kstage, uint32_t vstage,
                                          uint32_t b_lane_b, int kt, bool need_mask,
                                          int row_g0, int lane,
                                          float O[8][4], float* mst, float* lst) {
    float acc[8][4];
#pragma unroll
    for (int nb = 0; nb < 8; nb++)
#pragma unroll
        for (int j = 0; j < 4; j++) acc[nb][j] = 0.f;

    // S = Q K^T, 4 k16 steps over D=64
#pragma unroll
    for (int s = 0; s < 4; s++) {
        uint32_t af[4];
        LDSM_X4(af[0], af[1], af[2], af[3], a_addr + s * 32);
#pragma unroll
        for (int nt2 = 0; nt2 < 4; nt2++) {
            uint32_t bf[4];
            LDSM_X4(bf[0], bf[1], bf[2], bf[3],
                    kstage + b_lane_b + (uint32_t)(nt2 * 16 * QS2 + s * 16) * 2);
            MMAH16816(acc[2 * nt2],     af, (&bf[0]));
            MMAH16816(acc[2 * nt2 + 1], af, (&bf[2]));
        }
    }

    // scale + causal mask
#pragma unroll
    for (int nb = 0; nb < 8; nb++)
#pragma unroll
        for (int j = 0; j < 4; j++) {
            float v = acc[nb][j] * 0.125f;
            if (need_mask) {
                int col = kt * 64 + nb * 8 + 2 * (lane & 3) + (j & 1);
                int row = row_g0 + ((j >> 1) << 3);
                if (col > row) v = -1e30f;
            }
            acc[nb][j] = v;
        }

    // online softmax (rows r and r+8)
    float mx0 = -1e30f, mx1 = -1e30f;
#pragma unroll
    for (int nb = 0; nb < 8; nb++) {
        mx0 = fmaxf(mx0, fmaxf(acc[nb][0], acc[nb][1]));
        mx1 = fmaxf(mx1, fmaxf(acc[nb][2], acc[nb][3]));
    }
    mx0 = fmaxf(mx0, __shfl_xor_sync(0xffffffffu, mx0, 1));
    mx0 = fmaxf(mx0, __shfl_xor_sync(0xffffffffu, mx0, 2));
    mx1 = fmaxf(mx1, __shfl_xor_sync(0xffffffffu, mx1, 1));
    mx1 = fmaxf(mx1, __shfl_xor_sync(0xffffffffu, mx1, 2));
    float mn0 = fmaxf(mst[0], mx0), mn1 = fmaxf(mst[1], mx1);
    float al0 = __expf(mst[0] - mn0), al1 = __expf(mst[1] - mn1);
    float s0 = 0.f, s1 = 0.f;
#pragma unroll
    for (int nb = 0; nb < 8; nb++) {
        acc[nb][0] = __expf(acc[nb][0] - mn0);
        acc[nb][1] = __expf(acc[nb][1] - mn0);
        acc[nb][2] = __expf(acc[nb][2] - mn1);
        acc[nb][3] = __expf(acc[nb][3] - mn1);
        s0 += acc[nb][0] + acc[nb][1];
        s1 += acc[nb][2] + acc[nb][3];
    }
    s0 += __shfl_xor_sync(0xffffffffu, s0, 1);
    s0 += __shfl_xor_sync(0xffffffffu, s0, 2);
    s1 += __shfl_xor_sync(0xffffffffu, s1, 1);
    s1 += __shfl_xor_sync(0xffffffffu, s1, 2);
    lst[0] = lst[0] * al0 + s0;
    lst[1] = lst[1] * al1 + s1;
    mst[0] = mn0;
    mst[1] = mn1;
#pragma unroll
    for (int nb = 0; nb < 8; nb++) {
        O[nb][0] *= al0; O[nb][1] *= al0;
        O[nb][2] *= al1; O[nb][3] *= al1;
    }

    // O += P V (register-direct fp16 P fragments)
#pragma unroll
    for (int s = 0; s < 4; s++) {
        uint32_t ah[4];
        ah[0] = packh(acc[2 * s][0],     acc[2 * s][1]);
        ah[1] = packh(acc[2 * s][2],     acc[2 * s][3]);
        ah[2] = packh(acc[2 * s + 1][0], acc[2 * s + 1][1]);
        ah[3] = packh(acc[2 * s + 1][2], acc[2 * s + 1][3]);
#pragma unroll
        for (int nt2 = 0; nt2 < 4; nt2++) {
            uint32_t bv[4];
            LDSM_X4(bv[0], bv[1], bv[2], bv[3],
                    vstage + b_lane_b + (uint32_t)(nt2 * 16 * QS2 + s * 16) * 2);
            MMAH16816(O[2 * nt2],     ah, (&bv[0]));
            MMAH16816(O[2 * nt2 + 1], ah, (&bv[2]));
        }
    }
}

__global__ void __launch_bounds__(256) flash_mma(
    const __half* __restrict__ Q1f, const __half* __restrict__ Q2f,
    const __half* __restrict__ K1f, const __half* __restrict__ K2f,
    const __half* __restrict__ Vtg, const float* __restrict__ lam_p,
    __nv_bfloat16* __restrict__ Ab) {
    extern __shared__ __half sfb[];
    const uint32_t sb = smem_u32(sfb);
    const int tid = threadIdx.x, wid = tid >> 5, lane = tid & 31;
    const int qrev = gridDim.x - 1 - blockIdx.x;    // heavy CTAs first
    const int q0 = qrev * 128;
    const int h = blockIdx.y, b = blockIdx.z;
    const int bh = b * HH + h;
    const int nkv = 2 * qrev + 2;

    const __half* Q1g = Q1f + ((size_t)bh * TT + q0) * DD;
    const __half* Q2g = Q2f + ((size_t)bh * TT + q0) * DD;
    const __half* K1g = K1f + (size_t)bh * TT * DD;
    const __half* K2g = K2f + (size_t)bh * TT * DD;
    const __half* Vg  = Vtg + (size_t)bh * DD * TT;

    // Q tiles via cp.async: 128 rows x 64 fp16
    {
        int row = tid >> 1, seg = (tid & 1) * 32;
        uint32_t d1 = sb + (uint32_t)(FL_Q1 + row * QS2 + seg) * 2;
        uint32_t d2 = sb + (uint32_t)(FL_Q2 + row * QS2 + seg) * 2;
        const __half* s1 = Q1g + row * DD + seg;
        const __half* s2 = Q2g + row * DD + seg;
#pragma unroll
        for (int j = 0; j < 4; j++) { CP16(d1 + j * 16, s1 + j * 8); CP16(d2 + j * 16, s2 + j * 8); }
    }
    fl_load_kv(sb, 0, 0, tid, K1g, K2g, Vg);
    CP_COMMIT();

    float O1[8][4], O2[8][4];
#pragma unroll
    for (int nb = 0; nb < 8; nb++)
#pragma unroll
        for (int j = 0; j < 4; j++) { O1[nb][j] = 0.f; O2[nb][j] = 0.f; }
    float m1[2] = {-1e30f, -1e30f}, l1[2] = {0.f, 0.f};
    float m2[2] = {-1e30f, -1e30f}, l2[2] = {0.f, 0.f};

    const int row_g0 = q0 + wid * 16 + (lane >> 2);
    const uint32_t a_lane = (uint32_t)((lane & 15) * QS2 + (lane >> 4) * 8) * 2;
    const uint32_t aQ1 = sb + (uint32_t)(FL_Q1 + wid * 16 * QS2) * 2 + a_lane;
    const uint32_t aQ2 = sb + (uint32_t)(FL_Q2 + wid * 16 * QS2) * 2 + a_lane;
    const uint32_t b_lane_b = (uint32_t)((((lane >> 4) & 1) * 8 + (lane & 7)) * QS2 +
                                         ((lane >> 3) & 1) * 8) * 2;

    for (int kt = 0; kt < nkv; kt++) {
        if (kt + 1 < nkv) {
            fl_load_kv(sb, (kt + 1) & 1, kt + 1, tid, K1g, K2g, Vg);
            CP_COMMIT();
            CP_WAIT(1);
        } else {
            CP_WAIT(0);
        }
        __syncthreads();
        const uint32_t st = sb + (uint32_t)(FL_ST0 + (kt & 1) * FL_STAGE) * 2;
        const bool msk = (kt >= nkv - 2);
        fl_stream(aQ1, st,             st + 2 * FL_KV * 2, b_lane_b, kt, msk, row_g0, lane, O1, m1, l1);
        fl_stream(aQ2, st + FL_KV * 2, st + 2 * FL_KV * 2, b_lane_b, kt, msk, row_g0, lane, O2, m2, l2);
        __syncthreads();
    }

    // epilogue: out = O1/l1 - lam*O2/l2, write split-bf16 [hi|lo] into Ab
    float lamv = fminf(fmaxf(lam_p[h], 0.f), 1.f);
    float i10 = 1.f / l1[0], i11 = 1.f / l1[1];
    float i20 = lamv / l2[0], i21 = lamv / l2[1];
    const int row0 = q0 + wid * 16 + (lane >> 2);
    const int colb = h * 64 + 2 * (lane & 3);
    size_t rb0 = (size_t)(b * TT + row0) * KW;
    size_t rb1 = (size_t)(b * TT + row0 + 8) * KW;
#pragma unroll
    for (int nb = 0; nb < 8; nb++) {
        int col = colb + nb * 8;
        float x0 = O1[nb][0] * i10 - O2[nb][0] * i20;
        float x1 = O1[nb][1] * i10 - O2[nb][1] * i20;
        float y0 = O1[nb][2] * i11 - O2[nb][2] * i21;
        float y1 = O1[nb][3] * i11 - O2[nb][3] * i21;
        uint32_t hx = packbf(x0, x1);
        __nv_bfloat162 hv = *(__nv_bfloat162*)&hx;
        float2 hf = __bfloat1622float2(hv);
        uint32_t lx = packbf(x0 - hf.x, x1 - hf.y);
        *(uint32_t*)&Ab[rb0 + col] = hx;
        *(uint32_t*)&Ab[rb0 + 1024 + col] = lx;
        uint32_t hy = packbf(y0, y1);
        __nv_bfloat162 hv2 = *(__nv_bfloat162*)&hy;
        float2 hf2 = __bfloat1622float2(hv2);
        uint32_t ly = packbf(y0 - hf2.x, y1 - hf2.y);
        *(uint32_t*)&Ab[rb1 + col] = hy;
        *(uint32_t*)&Ab[rb1 + 1024 + col] = ly;
    }
}

// ---------------- launch ----------------
extern "C" void kernel_launch(void* const* d_in, const int* in_sizes, int n_in,
                              void* d_out, int out_size) {
    const float* x    = (const float*)d_in[0];
    const float* Wqkv = (const float*)d_in[2];
    const float* Wout = (const float*)d_in[3];
    const float* lam  = (const float*)d_in[4];
    float* out = (float*)d_out;

    float* qkv = nullptr;
    __nv_bfloat16 *Ab = nullptr, *Bq = nullptr, *Bo = nullptr;
    __half *Q1f = nullptr, *Q2f = nullptr, *K1f = nullptr, *K2f = nullptr, *Vt = nullptr;
    cudaGetSymbolAddress((void**)&qkv, g_qkv);
    cudaGetSymbolAddress((void**)&Ab,  g_Ab);
    cudaGetSymbolAddress((void**)&Bq,  g_Bq);
    cudaGetSymbolAddress((void**)&Bo,  g_Bo);
    cudaGetSymbolAddress((void**)&Q1f, g_Q1f);
    cudaGetSymbolAddress((void**)&Q2f, g_Q2f);
    cudaGetSymbolAddress((void**)&K1f, g_K1f);
    cudaGetSymbolAddress((void**)&K2f, g_K2f);
    cudaGetSymbolAddress((void**)&Vt,  g_Vt);

    cudaFuncSetAttribute(gemm_mma, cudaFuncAttributeMaxDynamicSharedMemorySize, GEMM_SMEM);
    cudaFuncSetAttribute(flash_mma, cudaFuncAttributeMaxDynamicSharedMemorySize, FL_SMEM_BYTES);

    // weight + input split conversions
    splitT<<<dim3(NQKV / 32, DM / 32), dim3(32, 8)>>>(Wqkv, Bq, NQKV);
    splitT<<<dim3(DM / 32, DM / 32), dim3(32, 8)>>>(Wout, Bo, DM);
    split_rows<<<(BT * DM + 255) / 256, 256>>>(x, Ab, BT * DM);

    // 1) QKV projection (HMMA, split-bf16 combos)
    gemm_mma<<<dim3(NQKV / 128, BT / 128), 256, GEMM_SMEM>>>(Ab, Bq, qkv, NQKV);

    // 2) flash operand prep (fp16)
    qkv_split<<<(BB * HH * TT * DD + 255) / 256, 256>>>(qkv, Q1f, Q2f, K1f, K2f);
    v_transpose<<<dim3(TT / 64, BB * HH), 256>>>(qkv, Vt);

    // 3) dual flash attention (fp16 HMMA); writes split-bf16 attn into Ab
    flash_mma<<<dim3(TT / 128, HH, BB), 256, FL_SMEM_BYTES>>>(Q1f, Q2f, K1f, K2f, Vt, lam, Ab);

    // 4) output projection (HMMA, split-bf16 combos)
    gemm_mma<<<dim3(DM / 128, BT / 128), 256, GEMM_SMEM>>>(Ab, Bo, out, DM);
}